// round 1
// baseline (speedup 1.0000x reference)
#include <cuda_runtime.h>

#define N_NODES 50000
#define N_EDGES 800000
#define IN_DIM  256
#define MAP_DIM 64
#define H_HEADS 4
#define O_DIM   64

// ---------------- scratch (device globals; no allocation allowed) ----------------
__device__ float  g_z[N_NODES * MAP_DIM];          // x @ gate_m_W + b        [N,64]
__device__ float  g_feat[N_NODES * IN_DIM];        // x @ W_gat               [N,256]
__device__ float4 g_el[N_NODES];                   // per-node el[h]          [N,4]
__device__ float4 g_er[N_NODES];                   // per-node er[h]          [N,4]
__device__ float4 g_xc[N_NODES];                   // x @ gate_fn_W[0:256]    [N,4]
__device__ float4 g_px[N_NODES];                   // x @ gate_fn_W[320:576]  [N,4]
__device__ int    g_deg[N_NODES];
__device__ int    g_off[N_NODES + 1];
__device__ int    g_cur[N_NODES];
__device__ int    g_srcs[N_EDGES];                 // src sorted by dst (CSR)
__device__ float  g_gated[N_NODES * O_DIM];        // gated merge input       [N,64]

__device__ __forceinline__ float lrelu(float v) { return v > 0.f ? v : 0.2f * v; }
__device__ __forceinline__ float dot4(float4 a, float4 b) {
    return a.x * b.x + a.y * b.y + a.z * b.z + a.w * b.w;
}

// ---------------- CSR build ----------------
__global__ void k_zero_deg() {
    int i = blockIdx.x * blockDim.x + threadIdx.x;
    if (i < N_NODES) g_deg[i] = 0;
}

__global__ void k_hist(const int* __restrict__ dst) {
    int e = blockIdx.x * blockDim.x + threadIdx.x;
    if (e < N_EDGES) atomicAdd(&g_deg[dst[e]], 1);
}

__global__ __launch_bounds__(1024) void k_scan() {
    __shared__ int wsum[32];
    int t = threadIdx.x, lane = t & 31, w = t >> 5;
    const int CH = (N_NODES + 1023) / 1024;
    int b = t * CH; if (b > N_NODES) b = N_NODES;
    int e = b + CH; if (e > N_NODES) e = N_NODES;
    int s = 0;
    for (int i = b; i < e; i++) s += g_deg[i];
    int v = s;
    #pragma unroll
    for (int d = 1; d < 32; d <<= 1) {
        int u = __shfl_up_sync(0xffffffffu, v, d);
        if (lane >= d) v += u;
    }
    if (lane == 31) wsum[w] = v;
    __syncthreads();
    if (w == 0) {
        int ws = wsum[lane];
        #pragma unroll
        for (int d = 1; d < 32; d <<= 1) {
            int u = __shfl_up_sync(0xffffffffu, ws, d);
            if (lane >= d) ws += u;
        }
        wsum[lane] = ws;
    }
    __syncthreads();
    int run = (w ? wsum[w - 1] : 0) + (v - s);   // exclusive prefix at chunk start
    for (int i = b; i < e; i++) {
        g_off[i] = run; g_cur[i] = run;
        run += g_deg[i];
    }
    if (b < N_NODES && e == N_NODES) g_off[N_NODES] = run;
}

__global__ void k_scatter(const int* __restrict__ src, const int* __restrict__ dst) {
    int e = blockIdx.x * blockDim.x + threadIdx.x;
    if (e < N_EDGES) {
        int p = atomicAdd(&g_cur[dst[e]], 1);
        g_srcs[p] = src[e];
    }
}

// ---------------- tiled SGEMM: C[M,Nn] = A[M,K] @ W[K,Nn] (+bias) (+=) ----------------
// BM=128, BN=64, BK=16, 256 threads, 8x4 microtile.
// asel: 0 = external A, 1 = g_gated.  csel: 0 = external C, 1 = g_z, 2 = g_feat.
__global__ __launch_bounds__(256) void k_sgemm(
    const float* __restrict__ Aext, int asel,
    const float* __restrict__ W, const float* __restrict__ bias,
    float* __restrict__ Cext, int csel,
    int M, int K, int Nn, int accumulate)
{
    const float* A = (asel == 1) ? g_gated : Aext;
    float* C = (csel == 1) ? g_z : (csel == 2 ? g_feat : Cext);

    __shared__ float As[16][128];
    __shared__ float Bs[16][64];
    int tid = threadIdx.x;
    int rowBase = blockIdx.x * 128;
    int colBase = blockIdx.y * 64;
    int tx = tid & 15, ty = tid >> 4;
    int r0 = ty * 8, c0 = tx * 4;
    int arow = tid & 127, ak = (tid >> 7) << 2;   // ak in {0,4}
    const float* Ap = A + (size_t)(rowBase + arow) * K;
    bool aok = (rowBase + arow) < M;
    float acc[8][4];
    #pragma unroll
    for (int i = 0; i < 8; i++)
        #pragma unroll
        for (int j = 0; j < 4; j++) acc[i][j] = 0.f;

    for (int k0 = 0; k0 < K; k0 += 16) {
        float4 a0 = make_float4(0, 0, 0, 0), a1 = a0;
        if (aok) {
            a0 = *(const float4*)(Ap + k0 + ak);
            a1 = *(const float4*)(Ap + k0 + ak + 8);
        }
        float4 b0 = *(const float4*)(W + (size_t)(k0 + ty) * Nn + colBase + c0);
        __syncthreads();
        As[ak + 0][arow] = a0.x; As[ak + 1][arow] = a0.y;
        As[ak + 2][arow] = a0.z; As[ak + 3][arow] = a0.w;
        As[ak + 8][arow] = a1.x; As[ak + 9][arow] = a1.y;
        As[ak + 10][arow] = a1.z; As[ak + 11][arow] = a1.w;
        *(float4*)&Bs[ty][c0] = b0;
        __syncthreads();
        #pragma unroll
        for (int kk = 0; kk < 16; kk++) {
            float4 A0 = *(const float4*)&As[kk][r0];
            float4 A1 = *(const float4*)&As[kk][r0 + 4];
            float4 B0 = *(const float4*)&Bs[kk][c0];
            float a[8] = {A0.x, A0.y, A0.z, A0.w, A1.x, A1.y, A1.z, A1.w};
            float b[4] = {B0.x, B0.y, B0.z, B0.w};
            #pragma unroll
            for (int i = 0; i < 8; i++)
                #pragma unroll
                for (int j = 0; j < 4; j++)
                    acc[i][j] = fmaf(a[i], b[j], acc[i][j]);
        }
    }

    float4 bb = make_float4(0, 0, 0, 0);
    if (bias) bb = *(const float4*)(bias + colBase + c0);
    #pragma unroll
    for (int i = 0; i < 8; i++) {
        int r = rowBase + r0 + i;
        if (r < M) {
            float* cp = C + (size_t)r * Nn + colBase + c0;
            float4 v = make_float4(acc[i][0] + bb.x, acc[i][1] + bb.y,
                                   acc[i][2] + bb.z, acc[i][3] + bb.w);
            if (accumulate) {
                float4 o = *(const float4*)cp;
                v.x += o.x; v.y += o.y; v.z += o.z; v.w += o.w;
            }
            *(float4*)cp = v;
        }
    }
}

// ---------------- per-node precompute: el, er, xc, px (one warp per node) ----------------
__global__ __launch_bounds__(256) void k_node_pre(
    const float* __restrict__ x, const float* __restrict__ attn_l,
    const float* __restrict__ attn_r, const float* __restrict__ gate_fn_W)
{
    __shared__ float4 s_al[64], s_ar[64], s_wx[256], s_wm[256];
    int tid = threadIdx.x;
    if (tid < 64) {
        s_al[tid] = ((const float4*)attn_l)[tid];
        s_ar[tid] = ((const float4*)attn_r)[tid];
    }
    s_wx[tid] = ((const float4*)gate_fn_W)[tid];         // rows 0..255 (x part)
    s_wm[tid] = ((const float4*)gate_fn_W)[320 + tid];   // rows 320..575 (mean part)
    __syncthreads();

    int lane = tid & 31;
    int n = blockIdx.x * 8 + (tid >> 5);
    if (n >= N_NODES) return;

    const float4* xr = (const float4*)(x + (size_t)n * IN_DIM);
    const float4* fr = (const float4*)(g_feat + (size_t)n * IN_DIM);
    float4 x0 = xr[lane], x1 = xr[lane + 32];
    float4 f0 = fr[lane], f1 = fr[lane + 32];

    float elA = dot4(f0, s_al[lane]);
    float elB = dot4(f1, s_al[lane + 32]);
    float erA = dot4(f0, s_ar[lane]);
    float erB = dot4(f1, s_ar[lane + 32]);

    float xa0[4] = {x0.x, x0.y, x0.z, x0.w};
    float xa1[4] = {x1.x, x1.y, x1.z, x1.w};
    float4 xc = make_float4(0, 0, 0, 0), px = make_float4(0, 0, 0, 0);
    #pragma unroll
    for (int t = 0; t < 4; t++) {
        float4 w0 = s_wx[4 * lane + t], w1 = s_wx[128 + 4 * lane + t];
        xc.x = fmaf(xa0[t], w0.x, fmaf(xa1[t], w1.x, xc.x));
        xc.y = fmaf(xa0[t], w0.y, fmaf(xa1[t], w1.y, xc.y));
        xc.z = fmaf(xa0[t], w0.z, fmaf(xa1[t], w1.z, xc.z));
        xc.w = fmaf(xa0[t], w0.w, fmaf(xa1[t], w1.w, xc.w));
        float4 m0 = s_wm[4 * lane + t], m1 = s_wm[128 + 4 * lane + t];
        px.x = fmaf(xa0[t], m0.x, fmaf(xa1[t], m1.x, px.x));
        px.y = fmaf(xa0[t], m0.y, fmaf(xa1[t], m1.y, px.y));
        px.z = fmaf(xa0[t], m0.z, fmaf(xa1[t], m1.z, px.z));
        px.w = fmaf(xa0[t], m0.w, fmaf(xa1[t], m1.w, px.w));
    }

    #pragma unroll
    for (int d = 8; d; d >>= 1) {
        elA += __shfl_xor_sync(0xffffffffu, elA, d);
        elB += __shfl_xor_sync(0xffffffffu, elB, d);
        erA += __shfl_xor_sync(0xffffffffu, erA, d);
        erB += __shfl_xor_sync(0xffffffffu, erB, d);
    }
    #pragma unroll
    for (int d = 16; d; d >>= 1) {
        xc.x += __shfl_xor_sync(0xffffffffu, xc.x, d);
        xc.y += __shfl_xor_sync(0xffffffffu, xc.y, d);
        xc.z += __shfl_xor_sync(0xffffffffu, xc.z, d);
        xc.w += __shfl_xor_sync(0xffffffffu, xc.w, d);
        px.x += __shfl_xor_sync(0xffffffffu, px.x, d);
        px.y += __shfl_xor_sync(0xffffffffu, px.y, d);
        px.z += __shfl_xor_sync(0xffffffffu, px.z, d);
        px.w += __shfl_xor_sync(0xffffffffu, px.w, d);
    }
    float elA1 = __shfl_sync(0xffffffffu, elA, 16);
    float elB1 = __shfl_sync(0xffffffffu, elB, 16);
    float erA1 = __shfl_sync(0xffffffffu, erA, 16);
    float erB1 = __shfl_sync(0xffffffffu, erB, 16);
    if (lane == 0) {
        g_el[n] = make_float4(elA, elA1, elB, elB1);
        g_er[n] = make_float4(erA, erA1, erB, erB1);
        g_xc[n] = xc;
        g_px[n] = px;
    }
}

// ---------------- aggregation: one warp per dst node ----------------
__global__ __launch_bounds__(256) void k_agg(
    const float* __restrict__ gate_fn_W, const float* __restrict__ gate_fn_b)
{
    __shared__ float4 s_wm[64];     // gate_fn_W rows 256..319 (max_z part)
    __shared__ float4 s_gb;
    int tid = threadIdx.x;
    if (tid < 64) s_wm[tid] = ((const float4*)gate_fn_W)[256 + tid];
    if (tid == 64) s_gb = *(const float4*)gate_fn_b;
    __syncthreads();

    int lane = tid & 31;
    int n = blockIdx.x * 8 + (tid >> 5);
    if (n >= N_NODES) return;

    int beg = g_off[n], end = g_off[n + 1];
    int deg = end - beg;
    float4* gout = (float4*)(g_gated + (size_t)n * O_DIM);
    if (deg == 0) {
        if (lane < 16) gout[lane] = make_float4(0, 0, 0, 0);
        return;
    }
    float4 er4 = g_er[n];

    // pass 1: per-head max of e over in-edges (edge-parallel across lanes)
    float4 m4 = make_float4(-1e30f, -1e30f, -1e30f, -1e30f);
    for (int j = beg + lane; j < end; j += 32) {
        int s = g_srcs[j];
        float4 el4 = g_el[s];
        m4.x = fmaxf(m4.x, lrelu(el4.x + er4.x));
        m4.y = fmaxf(m4.y, lrelu(el4.y + er4.y));
        m4.z = fmaxf(m4.z, lrelu(el4.z + er4.z));
        m4.w = fmaxf(m4.w, lrelu(el4.w + er4.w));
    }
    #pragma unroll
    for (int d = 16; d; d >>= 1) {
        m4.x = fmaxf(m4.x, __shfl_xor_sync(0xffffffffu, m4.x, d));
        m4.y = fmaxf(m4.y, __shfl_xor_sync(0xffffffffu, m4.y, d));
        m4.z = fmaxf(m4.z, __shfl_xor_sync(0xffffffffu, m4.z, d));
        m4.w = fmaxf(m4.w, __shfl_xor_sync(0xffffffffu, m4.w, d));
    }

    // pass 2: row-parallel accumulation (warp cooperates per edge)
    float4 f0 = make_float4(0, 0, 0, 0), f1 = f0, s4 = f0, pxs = f0;
    float2 mz = make_float2(-1e30f, -1e30f);
    const int hA = lane >> 4;     // first float4 covers head hA (0/1)
    for (int j = beg; j < end; j++) {
        int s = g_srcs[j];
        float2 zr = ((const float2*)(g_z + (size_t)s * MAP_DIM))[lane];
        mz.x = fmaxf(mz.x, zr.x); mz.y = fmaxf(mz.y, zr.y);
        float4 el4 = g_el[s];
        float4 ex;
        ex.x = __expf(lrelu(el4.x + er4.x) - m4.x);
        ex.y = __expf(lrelu(el4.y + er4.y) - m4.y);
        ex.z = __expf(lrelu(el4.z + er4.z) - m4.z);
        ex.w = __expf(lrelu(el4.w + er4.w) - m4.w);
        s4.x += ex.x; s4.y += ex.y; s4.z += ex.z; s4.w += ex.w;
        float4 p = g_px[s];
        pxs.x += p.x; pxs.y += p.y; pxs.z += p.z; pxs.w += p.w;
        const float4* frp = (const float4*)(g_feat + (size_t)s * IN_DIM);
        float exA = hA ? ex.y : ex.x;
        float exB = hA ? ex.w : ex.z;
        float4 fa = frp[lane], fb = frp[lane + 32];
        f0.x = fmaf(fa.x, exA, f0.x); f0.y = fmaf(fa.y, exA, f0.y);
        f0.z = fmaf(fa.z, exA, f0.z); f0.w = fmaf(fa.w, exA, f0.w);
        f1.x = fmaf(fb.x, exB, f1.x); f1.y = fmaf(fb.y, exB, f1.y);
        f1.z = fmaf(fb.z, exB, f1.z); f1.w = fmaf(fb.w, exB, f1.w);
    }

    float invdeg = 1.f / (float)deg;
    // gate logits: xc + (sum px)/deg + max_z @ W_m + b
    float4 wA = s_wm[2 * lane], wB = s_wm[2 * lane + 1];
    float4 gl;
    gl.x = mz.x * wA.x + mz.y * wB.x;
    gl.y = mz.x * wA.y + mz.y * wB.y;
    gl.z = mz.x * wA.z + mz.y * wB.z;
    gl.w = mz.x * wA.w + mz.y * wB.w;
    #pragma unroll
    for (int d = 16; d; d >>= 1) {
        gl.x += __shfl_xor_sync(0xffffffffu, gl.x, d);
        gl.y += __shfl_xor_sync(0xffffffffu, gl.y, d);
        gl.z += __shfl_xor_sync(0xffffffffu, gl.z, d);
        gl.w += __shfl_xor_sync(0xffffffffu, gl.w, d);
    }
    float4 xc = g_xc[n];
    float4 t = make_float4(xc.x + pxs.x * invdeg + gl.x + s_gb.x,
                           xc.y + pxs.y * invdeg + gl.y + s_gb.y,
                           xc.z + pxs.z * invdeg + gl.z + s_gb.z,
                           xc.w + pxs.w * invdeg + gl.w + s_gb.w);
    float4 gate = make_float4(1.f / (1.f + __expf(-t.x)), 1.f / (1.f + __expf(-t.y)),
                              1.f / (1.f + __expf(-t.z)), 1.f / (1.f + __expf(-t.w)));
    float4 sinv = make_float4(1.f / fmaxf(s4.x, 1e-16f), 1.f / fmaxf(s4.y, 1e-16f),
                              1.f / fmaxf(s4.z, 1e-16f), 1.f / fmaxf(s4.w, 1e-16f));
    float cA = hA ? gate.y * sinv.y : gate.x * sinv.x;
    float cB = hA ? gate.w * sinv.w : gate.z * sinv.z;
    float4 r = make_float4(f0.x * cA + f1.x * cB, f0.y * cA + f1.y * cB,
                           f0.z * cA + f1.z * cB, f0.w * cA + f1.w * cB);
    r.x += __shfl_xor_sync(0xffffffffu, r.x, 16);
    r.y += __shfl_xor_sync(0xffffffffu, r.y, 16);
    r.z += __shfl_xor_sync(0xffffffffu, r.z, 16);
    r.w += __shfl_xor_sync(0xffffffffu, r.w, 16);
    r.x *= 0.25f; r.y *= 0.25f; r.z *= 0.25f; r.w *= 0.25f;
    if (lane < 16) gout[lane] = r;
}

// ---------------- launch ----------------
extern "C" void kernel_launch(void* const* d_in, const int* in_sizes, int n_in,
                              void* d_out, int out_size)
{
    const float* x         = (const float*)d_in[0];
    const int*   src       = (const int*)d_in[1];
    const int*   dst       = (const int*)d_in[2];
    const float* W_gat     = (const float*)d_in[3];
    const float* attn_l    = (const float*)d_in[4];
    const float* attn_r    = (const float*)d_in[5];
    const float* gate_m_W  = (const float*)d_in[6];
    const float* gate_m_b  = (const float*)d_in[7];
    const float* gate_fn_W = (const float*)d_in[8];
    const float* gate_fn_b = (const float*)d_in[9];
    const float* merge_W   = (const float*)d_in[10];
    const float* merge_b   = (const float*)d_in[11];
    float* out = (float*)d_out;

    // CSR build (recomputed each launch; graph-capturable, no allocations)
    k_zero_deg<<<(N_NODES + 255) / 256, 256>>>();
    k_hist<<<(N_EDGES + 255) / 256, 256>>>(dst);
    k_scan<<<1, 1024>>>();
    k_scatter<<<(N_EDGES + 255) / 256, 256>>>(src, dst);

    // z = x @ gate_m_W + b   -> g_z
    k_sgemm<<<dim3((N_NODES + 127) / 128, MAP_DIM / 64), 256>>>(
        x, 0, gate_m_W, gate_m_b, nullptr, 1, N_NODES, IN_DIM, MAP_DIM, 0);
    // feat = x @ W_gat       -> g_feat
    k_sgemm<<<dim3((N_NODES + 127) / 128, IN_DIM / 64), 256>>>(
        x, 0, W_gat, nullptr, nullptr, 2, N_NODES, IN_DIM, IN_DIM, 0);
    // per-node el/er/xc/px
    k_node_pre<<<(N_NODES + 7) / 8, 256>>>(x, attn_l, attn_r, gate_fn_W);
    // edge aggregation + gate -> g_gated
    k_agg<<<(N_NODES + 7) / 8, 256>>>(gate_fn_W, gate_fn_b);
    // out = x @ merge_W[0:256] + merge_b
    k_sgemm<<<dim3((N_NODES + 127) / 128, 1), 256>>>(
        x, 0, merge_W, merge_b, out, 0, N_NODES, IN_DIM, O_DIM, 0);
    // out += gated @ merge_W[256:320]
    k_sgemm<<<dim3((N_NODES + 127) / 128, 1), 256>>>(
        nullptr, 1, merge_W + IN_DIM * O_DIM, nullptr, out, 0, N_NODES, O_DIM, O_DIM, 1);
}

// round 3
// speedup vs baseline: 1.2739x; 1.2739x over previous
#include <cuda_runtime.h>
#include <cuda_bf16.h>
#include <cstdint>

#define N_NODES 50000
#define N_EDGES 800000
#define IN_DIM  256
#define MAP_DIM 64
#define O_DIM   64
#define NCOLS   512      // padded fused GEMM width (400 real)

// ---------------- scratch (device globals) ----------------
__device__ float  g_z[N_NODES * MAP_DIM];
__device__ float  g_feat[N_NODES * IN_DIM];
__device__ float4 g_el[N_NODES];
__device__ float4 g_er[N_NODES];
__device__ float4 g_xc[N_NODES];
__device__ float4 g_px[N_NODES];
__device__ int    g_deg[N_NODES];
__device__ int    g_off[N_NODES + 1];
__device__ int    g_cur[N_NODES];
__device__ int    g_srcs[N_EDGES];
__device__ float  g_gated[N_NODES * O_DIM];
__device__ unsigned short g_wcat_hi[NCOLS * IN_DIM];   // [n][k] bf16 (B col-major for mma)
__device__ unsigned short g_wcat_lo[NCOLS * IN_DIM];
__device__ unsigned short g_x_hi[(size_t)N_NODES * IN_DIM];
__device__ unsigned short g_x_lo[(size_t)N_NODES * IN_DIM];

__device__ __forceinline__ float lrelu(float v) { return v > 0.f ? v : 0.2f * v; }

__device__ __forceinline__ uint32_t smem_u32(const void* p) {
    uint32_t a;
    asm("{ .reg .u64 t; cvta.to.shared.u64 t, %1; cvt.u32.u64 %0, t; }" : "=r"(a) : "l"(p));
    return a;
}
__device__ __forceinline__ void ldsm4(uint32_t* r, uint32_t addr) {
    asm volatile("ldmatrix.sync.aligned.m8n8.x4.shared.b16 {%0,%1,%2,%3}, [%4];"
        : "=r"(r[0]), "=r"(r[1]), "=r"(r[2]), "=r"(r[3]) : "r"(addr));
}
__device__ __forceinline__ void mma16816(float* c, const uint32_t* a, const uint32_t* b) {
    asm volatile("mma.sync.aligned.m16n8k16.row.col.f32.bf16.bf16.f32 "
        "{%0,%1,%2,%3}, {%4,%5,%6,%7}, {%8,%9}, {%0,%1,%2,%3};"
        : "+f"(c[0]), "+f"(c[1]), "+f"(c[2]), "+f"(c[3])
        : "r"(a[0]), "r"(a[1]), "r"(a[2]), "r"(a[3]), "r"(b[0]), "r"(b[1]));
}

// ---------------- CSR build ----------------
__global__ void k_zero_deg() {
    int i = blockIdx.x * blockDim.x + threadIdx.x;
    if (i < N_NODES) g_deg[i] = 0;
}
__global__ void k_hist(const int* __restrict__ dst) {
    int e = blockIdx.x * blockDim.x + threadIdx.x;
    if (e < N_EDGES) atomicAdd(&g_deg[dst[e]], 1);
}
__global__ __launch_bounds__(1024) void k_scan() {
    __shared__ int wsum[32];
    int t = threadIdx.x, lane = t & 31, w = t >> 5;
    const int CH = (N_NODES + 1023) / 1024;
    int b = t * CH; if (b > N_NODES) b = N_NODES;
    int e = b + CH; if (e > N_NODES) e = N_NODES;
    int s = 0;
    for (int i = b; i < e; i++) s += g_deg[i];
    int v = s;
    #pragma unroll
    for (int d = 1; d < 32; d <<= 1) {
        int u = __shfl_up_sync(0xffffffffu, v, d);
        if (lane >= d) v += u;
    }
    if (lane == 31) wsum[w] = v;
    __syncthreads();
    if (w == 0) {
        int ws = wsum[lane];
        #pragma unroll
        for (int d = 1; d < 32; d <<= 1) {
            int u = __shfl_up_sync(0xffffffffu, ws, d);
            if (lane >= d) ws += u;
        }
        wsum[lane] = ws;
    }
    __syncthreads();
    int run = (w ? wsum[w - 1] : 0) + (v - s);
    for (int i = b; i < e; i++) {
        g_off[i] = run; g_cur[i] = run;
        run += g_deg[i];
    }
    if (b < N_NODES && e == N_NODES) g_off[N_NODES] = run;
}
__global__ void k_scatter(const int* __restrict__ src, const int* __restrict__ dst) {
    int e = blockIdx.x * blockDim.x + threadIdx.x;
    if (e < N_EDGES) {
        int p = atomicAdd(&g_cur[dst[e]], 1);
        g_srcs[p] = src[e];
    }
}

// ---------------- x split into bf16 hi/lo ----------------
__global__ void k_split_x(const float* __restrict__ x) {
    size_t idx = (size_t)blockIdx.x * blockDim.x + threadIdx.x;  // over N*64 float4
    if (idx >= (size_t)N_NODES * 64) return;
    float4 v = ((const float4*)x)[idx];
    __nv_bfloat16 h0 = __float2bfloat16(v.x), h1 = __float2bfloat16(v.y);
    __nv_bfloat16 h2 = __float2bfloat16(v.z), h3 = __float2bfloat16(v.w);
    uint2 hh, ll;
    hh.x = (uint32_t)__bfloat16_as_ushort(h0) | ((uint32_t)__bfloat16_as_ushort(h1) << 16);
    hh.y = (uint32_t)__bfloat16_as_ushort(h2) | ((uint32_t)__bfloat16_as_ushort(h3) << 16);
    __nv_bfloat16 l0 = __float2bfloat16(v.x - __bfloat162float(h0));
    __nv_bfloat16 l1 = __float2bfloat16(v.y - __bfloat162float(h1));
    __nv_bfloat16 l2 = __float2bfloat16(v.z - __bfloat162float(h2));
    __nv_bfloat16 l3 = __float2bfloat16(v.w - __bfloat162float(h3));
    ll.x = (uint32_t)__bfloat16_as_ushort(l0) | ((uint32_t)__bfloat16_as_ushort(l1) << 16);
    ll.y = (uint32_t)__bfloat16_as_ushort(l2) | ((uint32_t)__bfloat16_as_ushort(l3) << 16);
    ((uint2*)g_x_hi)[idx] = hh;
    ((uint2*)g_x_lo)[idx] = ll;
}

// ---------------- weight concat + bf16 split: Wcat[n][k] ----------------
__global__ void k_prep_w(const float* __restrict__ W_gat, const float* __restrict__ attn_l,
                         const float* __restrict__ attn_r, const float* __restrict__ gate_m_W,
                         const float* __restrict__ merge_W, const float* __restrict__ gate_fn_W)
{
    int n = blockIdx.x;       // 0..511 output column
    int k = threadIdx.x;      // 0..255
    float v = 0.f;
    if (n < 256)      v = W_gat[k * 256 + n];
    else if (n < 320) v = gate_m_W[k * 64 + (n - 256)];
    else if (n < 384) v = merge_W[k * 64 + (n - 320)];
    else if (n < 388) v = gate_fn_W[k * 4 + (n - 384)];                // xc
    else if (n < 392) v = gate_fn_W[(320 + k) * 4 + (n - 388)];       // px (mean part)
    else if (n < 396) {                                               // el = x @ (W_gat . attn_l)
        int h = n - 392; float s = 0.f;
        for (int o = 0; o < 64; o++) s += W_gat[k * 256 + h * 64 + o] * attn_l[h * 64 + o];
        v = s;
    } else if (n < 400) {                                             // er
        int h = n - 396; float s = 0.f;
        for (int o = 0; o < 64; o++) s += W_gat[k * 256 + h * 64 + o] * attn_r[h * 64 + o];
        v = s;
    }
    __nv_bfloat16 hi = __float2bfloat16(v);
    float lo = v - __bfloat162float(hi);
    g_wcat_hi[n * 256 + k] = __bfloat16_as_ushort(hi);
    g_wcat_lo[n * 256 + k] = __bfloat16_as_ushort(__float2bfloat16(lo));
}

// ---------------- fused HMMA GEMM: C[128,256]/CTA, K=256, Kc=16 ----------------
// smem stride: 24 bf16 = 48B/row (conflict-free ldmatrix, 16B aligned)
#define SA_HI 0
#define SA_LO 6144
#define SB_HI 12288
#define SB_LO 24576
#define GEMM_SMEM 36864

__global__ __launch_bounds__(256, 1) void k_gemm_mma(
    const float* __restrict__ gate_m_b, const float* __restrict__ merge_b,
    float* __restrict__ out)
{
    __shared__ __align__(16) char sm[GEMM_SMEM];
    uint32_t sb = smem_u32(sm);
    int tid = threadIdx.x, w = tid >> 5, lane = tid & 31;
    int r0 = blockIdx.x * 128;
    int nb = blockIdx.y * 256;
    int wm = (w & 1) * 64, wn = (w >> 1) * 64;

    float acc[4][8][4];
    #pragma unroll
    for (int a = 0; a < 4; a++)
        #pragma unroll
        for (int b = 0; b < 8; b++)
            #pragma unroll
            for (int c = 0; c < 4; c++) acc[a][b][c] = 0.f;

    for (int ch = 0; ch < 16; ch++) {
        int k0 = ch * 16;
        __syncthreads();
        // A: 128 rows x 16 k (hi+lo): 256 uint4 tasks per buffer
        {
            int row = tid >> 1, kg = tid & 1;
            int gr = r0 + row;
            uint4 hv = make_uint4(0, 0, 0, 0), lv = hv;
            if (gr < N_NODES) {
                hv = *(const uint4*)(g_x_hi + (size_t)gr * 256 + k0 + kg * 8);
                lv = *(const uint4*)(g_x_lo + (size_t)gr * 256 + k0 + kg * 8);
            }
            *(uint4*)(sm + SA_HI + row * 48 + kg * 16) = hv;
            *(uint4*)(sm + SA_LO + row * 48 + kg * 16) = lv;
        }
        // B: 256 rows x 16 k (hi+lo): 512 uint4 tasks per buffer
        #pragma unroll
        for (int i = 0; i < 2; i++) {
            int q = tid + i * 256;
            int row = q >> 1, kg = q & 1;
            *(uint4*)(sm + SB_HI + row * 48 + kg * 16) =
                *(const uint4*)(g_wcat_hi + (size_t)(nb + row) * 256 + k0 + kg * 8);
            *(uint4*)(sm + SB_LO + row * 48 + kg * 16) =
                *(const uint4*)(g_wcat_lo + (size_t)(nb + row) * 256 + k0 + kg * 8);
        }
        __syncthreads();

        uint32_t aH[4][4], aL[4][4], bf[4][4];
        int arow = wm + (lane & 7) + ((lane & 8) ? 8 : 0);
        int acol = ((lane & 16) ? 16 : 0);   // bytes
        #pragma unroll
        for (int mt = 0; mt < 4; mt++) {
            ldsm4(aH[mt], sb + SA_HI + (arow + mt * 16) * 48 + acol);
            ldsm4(aL[mt], sb + SA_LO + (arow + mt * 16) * 48 + acol);
        }
        int brow = wn + (lane & 7) + ((lane & 16) ? 8 : 0);
        int bcol = ((lane & 8) ? 16 : 0);
        #pragma unroll
        for (int nt2 = 0; nt2 < 4; nt2++)
            ldsm4(bf[nt2], sb + SB_HI + (brow + nt2 * 16) * 48 + bcol);
        #pragma unroll
        for (int mt = 0; mt < 4; mt++)
            #pragma unroll
            for (int nt2 = 0; nt2 < 4; nt2++) {
                mma16816(acc[mt][nt2 * 2],     aH[mt], &bf[nt2][0]);
                mma16816(acc[mt][nt2 * 2 + 1], aH[mt], &bf[nt2][2]);
                mma16816(acc[mt][nt2 * 2],     aL[mt], &bf[nt2][0]);
                mma16816(acc[mt][nt2 * 2 + 1], aL[mt], &bf[nt2][2]);
            }
        #pragma unroll
        for (int nt2 = 0; nt2 < 4; nt2++)
            ldsm4(bf[nt2], sb + SB_LO + (brow + nt2 * 16) * 48 + bcol);
        #pragma unroll
        for (int mt = 0; mt < 4; mt++)
            #pragma unroll
            for (int nt2 = 0; nt2 < 4; nt2++) {
                mma16816(acc[mt][nt2 * 2],     aH[mt], &bf[nt2][0]);
                mma16816(acc[mt][nt2 * 2 + 1], aH[mt], &bf[nt2][2]);
            }
    }

    // epilogue: route columns
    int gcbase = nb + wn;
    #pragma unroll
    for (int nt = 0; nt < 8; nt++) {
        int gc = gcbase + nt * 8 + 2 * (lane & 3);
        if (gc >= 400) continue;
        float b0 = 0.f, b1 = 0.f;
        if (gc >= 256 && gc < 320) { b0 = gate_m_b[gc - 256]; b1 = gate_m_b[gc - 255]; }
        else if (gc >= 320 && gc < 384) { b0 = merge_b[gc - 320]; b1 = merge_b[gc - 319]; }
        #pragma unroll
        for (int mt = 0; mt < 4; mt++) {
            int row0 = r0 + wm + mt * 16 + (lane >> 2);
            #pragma unroll
            for (int h = 0; h < 2; h++) {
                int row = row0 + h * 8;
                if (row >= N_NODES) continue;
                float v0 = acc[mt][nt][h * 2] + b0;
                float v1 = acc[mt][nt][h * 2 + 1] + b1;
                if (gc < 256)
                    *(float2*)(g_feat + (size_t)row * 256 + gc) = make_float2(v0, v1);
                else if (gc < 320)
                    *(float2*)(g_z + (size_t)row * 64 + (gc - 256)) = make_float2(v0, v1);
                else if (gc < 384)
                    *(float2*)(out + (size_t)row * 64 + (gc - 320)) = make_float2(v0, v1);
                else {
                    int cc = gc - 384;
                    float* bp = cc < 4 ? (float*)g_xc : cc < 8 ? (float*)g_px
                              : cc < 12 ? (float*)g_el : (float*)g_er;
                    *(float2*)(bp + (size_t)row * 4 + (cc & 3)) = make_float2(v0, v1);
                }
            }
        }
    }
}

// ---------------- aggregation: one warp per dst node ----------------
__global__ __launch_bounds__(256) void k_agg(
    const float* __restrict__ gate_fn_W, const float* __restrict__ gate_fn_b)
{
    __shared__ float4 s_wm[64];
    __shared__ float4 s_gb;
    int tid = threadIdx.x;
    if (tid < 64) s_wm[tid] = ((const float4*)gate_fn_W)[256 + tid];
    if (tid == 64) s_gb = *(const float4*)gate_fn_b;
    __syncthreads();

    int lane = tid & 31;
    int n = blockIdx.x * 8 + (tid >> 5);
    if (n >= N_NODES) return;

    int beg = g_off[n], end = g_off[n + 1];
    int deg = end - beg;
    float4* gout = (float4*)(g_gated + (size_t)n * O_DIM);
    if (deg == 0) {
        if (lane < 16) gout[lane] = make_float4(0, 0, 0, 0);
        return;
    }
    float4 er4 = g_er[n];

    float4 m4 = make_float4(-1e30f, -1e30f, -1e30f, -1e30f);
    for (int j = beg + lane; j < end; j += 32) {
        int s = g_srcs[j];
        float4 el4 = g_el[s];
        m4.x = fmaxf(m4.x, lrelu(el4.x + er4.x));
        m4.y = fmaxf(m4.y, lrelu(el4.y + er4.y));
        m4.z = fmaxf(m4.z, lrelu(el4.z + er4.z));
        m4.w = fmaxf(m4.w, lrelu(el4.w + er4.w));
    }
    #pragma unroll
    for (int d = 16; d; d >>= 1) {
        m4.x = fmaxf(m4.x, __shfl_xor_sync(0xffffffffu, m4.x, d));
        m4.y = fmaxf(m4.y, __shfl_xor_sync(0xffffffffu, m4.y, d));
        m4.z = fmaxf(m4.z, __shfl_xor_sync(0xffffffffu, m4.z, d));
        m4.w = fmaxf(m4.w, __shfl_xor_sync(0xffffffffu, m4.w, d));
    }

    float4 f0 = make_float4(0, 0, 0, 0), f1 = f0, s4 = f0, pxs = f0;
    float2 mz = make_float2(-1e30f, -1e30f);
    const int hA = lane >> 4;
    for (int j = beg; j < end; j++) {
        int s = g_srcs[j];
        float2 zr = ((const float2*)(g_z + (size_t)s * MAP_DIM))[lane];
        mz.x = fmaxf(mz.x, zr.x); mz.y = fmaxf(mz.y, zr.y);
        float4 el4 = g_el[s];
        float4 ex;
        ex.x = __expf(lrelu(el4.x + er4.x) - m4.x);
        ex.y = __expf(lrelu(el4.y + er4.y) - m4.y);
        ex.z = __expf(lrelu(el4.z + er4.z) - m4.z);
        ex.w = __expf(lrelu(el4.w + er4.w) - m4.w);
        s4.x += ex.x; s4.y += ex.y; s4.z += ex.z; s4.w += ex.w;
        float4 p = g_px[s];
        pxs.x += p.x; pxs.y += p.y; pxs.z += p.z; pxs.w += p.w;
        const float4* frp = (const float4*)(g_feat + (size_t)s * IN_DIM);
        float exA = hA ? ex.y : ex.x;
        float exB = hA ? ex.w : ex.z;
        float4 fa = frp[lane], fb = frp[lane + 32];
        f0.x = fmaf(fa.x, exA, f0.x); f0.y = fmaf(fa.y, exA, f0.y);
        f0.z = fmaf(fa.z, exA, f0.z); f0.w = fmaf(fa.w, exA, f0.w);
        f1.x = fmaf(fb.x, exB, f1.x); f1.y = fmaf(fb.y, exB, f1.y);
        f1.z = fmaf(fb.z, exB, f1.z); f1.w = fmaf(fb.w, exB, f1.w);
    }

    float invdeg = 1.f / (float)deg;
    float4 wA = s_wm[2 * lane], wB = s_wm[2 * lane + 1];
    float4 gl;
    gl.x = mz.x * wA.x + mz.y * wB.x;
    gl.y = mz.x * wA.y + mz.y * wB.y;
    gl.z = mz.x * wA.z + mz.y * wB.z;
    gl.w = mz.x * wA.w + mz.y * wB.w;
    #pragma unroll
    for (int d = 16; d; d >>= 1) {
        gl.x += __shfl_xor_sync(0xffffffffu, gl.x, d);
        gl.y += __shfl_xor_sync(0xffffffffu, gl.y, d);
        gl.z += __shfl_xor_sync(0xffffffffu, gl.z, d);
        gl.w += __shfl_xor_sync(0xffffffffu, gl.w, d);
    }
    float4 xc = g_xc[n];
    float4 t = make_float4(xc.x + pxs.x * invdeg + gl.x + s_gb.x,
                           xc.y + pxs.y * invdeg + gl.y + s_gb.y,
                           xc.z + pxs.z * invdeg + gl.z + s_gb.z,
                           xc.w + pxs.w * invdeg + gl.w + s_gb.w);
    float4 gate = make_float4(1.f / (1.f + __expf(-t.x)), 1.f / (1.f + __expf(-t.y)),
                              1.f / (1.f + __expf(-t.z)), 1.f / (1.f + __expf(-t.w)));
    float4 sinv = make_float4(1.f / fmaxf(s4.x, 1e-16f), 1.f / fmaxf(s4.y, 1e-16f),
                              1.f / fmaxf(s4.z, 1e-16f), 1.f / fmaxf(s4.w, 1e-16f));
    float cA = hA ? gate.y * sinv.y : gate.x * sinv.x;
    float cB = hA ? gate.w * sinv.w : gate.z * sinv.z;
    float4 r = make_float4(f0.x * cA + f1.x * cB, f0.y * cA + f1.y * cB,
                           f0.z * cA + f1.z * cB, f0.w * cA + f1.w * cB);
    r.x += __shfl_xor_sync(0xffffffffu, r.x, 16);
    r.y += __shfl_xor_sync(0xffffffffu, r.y, 16);
    r.z += __shfl_xor_sync(0xffffffffu, r.z, 16);
    r.w += __shfl_xor_sync(0xffffffffu, r.w, 16);
    r.x *= 0.25f; r.y *= 0.25f; r.z *= 0.25f; r.w *= 0.25f;
    if (lane < 16) gout[lane] = r;
}

// ---------------- out += gated @ merge_W2 (fp32, small) ----------------
__global__ __launch_bounds__(256) void k_merge2(
    const float* __restrict__ W2, float* __restrict__ out)
{
    __shared__ float As[16][128];
    __shared__ float Bs[16][64];
    int tid = threadIdx.x;
    int rowBase = blockIdx.x * 128;
    int tx = tid & 15, ty = tid >> 4;
    int r0 = ty * 8, c0 = tx * 4;
    int arow = tid & 127, ak = (tid >> 7) << 2;
    const float* Ap = g_gated + (size_t)(rowBase + arow) * 64;
    bool aok = (rowBase + arow) < N_NODES;
    float acc[8][4];
    #pragma unroll
    for (int i = 0; i < 8; i++)
        #pragma unroll
        for (int j = 0; j < 4; j++) acc[i][j] = 0.f;

    for (int k0 = 0; k0 < 64; k0 += 16) {
        float4 a0 = make_float4(0, 0, 0, 0), a1 = a0;
        if (aok) {
            a0 = *(const float4*)(Ap + k0 + ak);
            a1 = *(const float4*)(Ap + k0 + ak + 8);
        }
        float4 b0 = *(const float4*)(W2 + (size_t)(k0 + ty) * 64 + c0);
        __syncthreads();
        As[ak + 0][arow] = a0.x; As[ak + 1][arow] = a0.y;
        As[ak + 2][arow] = a0.z; As[ak + 3][arow] = a0.w;
        As[ak + 8][arow] = a1.x; As[ak + 9][arow] = a1.y;
        As[ak + 10][arow] = a1.z; As[ak + 11][arow] = a1.w;
        *(float4*)&Bs[ty][c0] = b0;
        __syncthreads();
        #pragma unroll
        for (int kk = 0; kk < 16; kk++) {
            float4 A0 = *(const float4*)&As[kk][r0];
            float4 A1 = *(const float4*)&As[kk][r0 + 4];
            float4 B0 = *(const float4*)&Bs[kk][c0];
            float a[8] = {A0.x, A0.y, A0.z, A0.w, A1.x, A1.y, A1.z, A1.w};
            float b[4] = {B0.x, B0.y, B0.z, B0.w};
            #pragma unroll
            for (int i = 0; i < 8; i++)
                #pragma unroll
                for (int j = 0; j < 4; j++)
                    acc[i][j] = fmaf(a[i], b[j], acc[i][j]);
        }
    }
    #pragma unroll
    for (int i = 0; i < 8; i++) {
        int r = rowBase + r0 + i;
        if (r < N_NODES) {
            float* cp = out + (size_t)r * 64 + c0;
            float4 o = *(const float4*)cp;
            o.x += acc[i][0]; o.y += acc[i][1]; o.z += acc[i][2]; o.w += acc[i][3];
            *(float4*)cp = o;
        }
    }
}

// ---------------- launch ----------------
extern "C" void kernel_launch(void* const* d_in, const int* in_sizes, int n_in,
                              void* d_out, int out_size)
{
    const float* x         = (const float*)d_in[0];
    const int*   src       = (const int*)d_in[1];
    const int*   dst       = (const int*)d_in[2];
    const float* W_gat     = (const float*)d_in[3];
    const float* attn_l    = (const float*)d_in[4];
    const float* attn_r    = (const float*)d_in[5];
    const float* gate_m_W  = (const float*)d_in[6];
    const float* gate_m_b  = (const float*)d_in[7];
    const float* gate_fn_W = (const float*)d_in[8];
    const float* gate_fn_b = (const float*)d_in[9];
    const float* merge_W   = (const float*)d_in[10];
    const float* merge_b   = (const float*)d_in[11];
    float* out = (float*)d_out;

    // CSR build
    k_zero_deg<<<(N_NODES + 255) / 256, 256>>>();
    k_hist<<<(N_EDGES + 255) / 256, 256>>>(dst);
    k_scan<<<1, 1024>>>();
    k_scatter<<<(N_EDGES + 255) / 256, 256>>>(src, dst);

    // bf16 splits + fused HMMA GEMM
    k_split_x<<<(N_NODES * 64 + 255) / 256, 256>>>(x);
    k_prep_w<<<NCOLS, 256>>>(W_gat, attn_l, attn_r, gate_m_W, merge_W, gate_fn_W);
    k_gemm_mma<<<dim3((N_NODES + 127) / 128, 2), 256>>>(gate_m_b, merge_b, out);

    // edge aggregation + gate
    k_agg<<<(N_NODES + 7) / 8, 256>>>(gate_fn_W, gate_fn_b);

    // out += gated @ merge_W[256:320]
    k_merge2<<<(N_NODES + 127) / 128, 256>>>(merge_W + 256 * 64, out);
}

// round 4
// speedup vs baseline: 1.4366x; 1.1277x over previous
#include <cuda_runtime.h>
#include <cuda_bf16.h>
#include <cstdint>

#define N_NODES 50000
#define N_EDGES 800000
#define IN_DIM  256
#define NCOLS   512

// ---------------- scratch ----------------
__device__ unsigned short g_zb[N_NODES * 64];          // z bf16
__device__ unsigned short g_featb[(size_t)N_NODES * 256]; // feat bf16
__device__ float4 g_el[N_NODES];
__device__ float4 g_er[N_NODES];
__device__ float4 g_xc[N_NODES];
__device__ float4 g_px[N_NODES];
__device__ int    g_deg[N_NODES];
__device__ int    g_off[N_NODES + 1];
__device__ int    g_cur[N_NODES];
__device__ int    g_srcs[N_EDGES];
__device__ unsigned short g_wcat_hi[NCOLS * IN_DIM];
__device__ unsigned short g_wcat_lo[NCOLS * IN_DIM];
__device__ unsigned short g_x_hi[(size_t)N_NODES * IN_DIM];
__device__ unsigned short g_x_lo[(size_t)N_NODES * IN_DIM];

__device__ __forceinline__ float lrelu(float v) { return v > 0.f ? v : 0.2f * v; }
__device__ __forceinline__ float sel4(float4 v, int h) {
    float r = v.x;
    r = (h == 1) ? v.y : r;
    r = (h == 2) ? v.z : r;
    r = (h == 3) ? v.w : r;
    return r;
}
__device__ __forceinline__ float bflo(uint32_t u) { return __uint_as_float(u << 16); }
__device__ __forceinline__ float bfhi(uint32_t u) { return __uint_as_float(u & 0xFFFF0000u); }
__device__ __forceinline__ uint32_t packbf(float a, float b) {
    return (uint32_t)__bfloat16_as_ushort(__float2bfloat16(a)) |
           ((uint32_t)__bfloat16_as_ushort(__float2bfloat16(b)) << 16);
}

__device__ __forceinline__ uint32_t smem_u32(const void* p) {
    uint32_t a;
    asm("{ .reg .u64 t; cvta.to.shared.u64 t, %1; cvt.u32.u64 %0, t; }" : "=r"(a) : "l"(p));
    return a;
}
__device__ __forceinline__ void ldsm4(uint32_t* r, uint32_t addr) {
    asm volatile("ldmatrix.sync.aligned.m8n8.x4.shared.b16 {%0,%1,%2,%3}, [%4];"
        : "=r"(r[0]), "=r"(r[1]), "=r"(r[2]), "=r"(r[3]) : "r"(addr));
}
__device__ __forceinline__ void mma16816(float* c, const uint32_t* a, const uint32_t* b) {
    asm volatile("mma.sync.aligned.m16n8k16.row.col.f32.bf16.bf16.f32 "
        "{%0,%1,%2,%3}, {%4,%5,%6,%7}, {%8,%9}, {%0,%1,%2,%3};"
        : "+f"(c[0]), "+f"(c[1]), "+f"(c[2]), "+f"(c[3])
        : "r"(a[0]), "r"(a[1]), "r"(a[2]), "r"(a[3]), "r"(b[0]), "r"(b[1]));
}
__device__ __forceinline__ void cpa16(uint32_t dst, const void* src, uint32_t sz) {
    asm volatile("cp.async.cg.shared.global [%0], [%1], 16, %2;"
        :: "r"(dst), "l"(src), "r"(sz) : "memory");
}
#define CPA_COMMIT() asm volatile("cp.async.commit_group;" ::: "memory")
#define CPA_WAIT1()  asm volatile("cp.async.wait_group 1;" ::: "memory")
#define CPA_WAIT0()  asm volatile("cp.async.wait_group 0;" ::: "memory")

// ---------------- CSR build ----------------
__global__ void k_zero_deg() {
    int i = blockIdx.x * blockDim.x + threadIdx.x;
    if (i < N_NODES) g_deg[i] = 0;
}
__global__ void k_hist(const int* __restrict__ dst) {
    int e = blockIdx.x * blockDim.x + threadIdx.x;
    if (e < N_EDGES) atomicAdd(&g_deg[dst[e]], 1);
}
__global__ __launch_bounds__(1024) void k_scan() {
    __shared__ int wsum[32];
    int t = threadIdx.x, lane = t & 31, w = t >> 5;
    const int CH = (N_NODES + 1023) / 1024;
    int b = t * CH; if (b > N_NODES) b = N_NODES;
    int e = b + CH; if (e > N_NODES) e = N_NODES;
    int s = 0;
    for (int i = b; i < e; i++) s += g_deg[i];
    int v = s;
    #pragma unroll
    for (int d = 1; d < 32; d <<= 1) {
        int u = __shfl_up_sync(0xffffffffu, v, d);
        if (lane >= d) v += u;
    }
    if (lane == 31) wsum[w] = v;
    __syncthreads();
    if (w == 0) {
        int ws = wsum[lane];
        #pragma unroll
        for (int d = 1; d < 32; d <<= 1) {
            int u = __shfl_up_sync(0xffffffffu, ws, d);
            if (lane >= d) ws += u;
        }
        wsum[lane] = ws;
    }
    __syncthreads();
    int run = (w ? wsum[w - 1] : 0) + (v - s);
    for (int i = b; i < e; i++) {
        g_off[i] = run; g_cur[i] = run;
        run += g_deg[i];
    }
    if (b < N_NODES && e == N_NODES) g_off[N_NODES] = run;
}
__global__ void k_scatter(const int* __restrict__ src, const int* __restrict__ dst) {
    int e = blockIdx.x * blockDim.x + threadIdx.x;
    if (e < N_EDGES) {
        int p = atomicAdd(&g_cur[dst[e]], 1);
        g_srcs[p] = src[e];
    }
}

// ---------------- x split ----------------
__global__ void k_split_x(const float* __restrict__ x) {
    size_t idx = (size_t)blockIdx.x * blockDim.x + threadIdx.x;
    if (idx >= (size_t)N_NODES * 64) return;
    float4 v = ((const float4*)x)[idx];
    __nv_bfloat16 h0 = __float2bfloat16(v.x), h1 = __float2bfloat16(v.y);
    __nv_bfloat16 h2 = __float2bfloat16(v.z), h3 = __float2bfloat16(v.w);
    uint2 hh, ll;
    hh.x = (uint32_t)__bfloat16_as_ushort(h0) | ((uint32_t)__bfloat16_as_ushort(h1) << 16);
    hh.y = (uint32_t)__bfloat16_as_ushort(h2) | ((uint32_t)__bfloat16_as_ushort(h3) << 16);
    ll.x = packbf(v.x - __bfloat162float(h0), v.y - __bfloat162float(h1));
    ll.y = packbf(v.z - __bfloat162float(h2), v.w - __bfloat162float(h3));
    ((uint2*)g_x_hi)[idx] = hh;
    ((uint2*)g_x_lo)[idx] = ll;
}

// ---------------- weight concat ----------------
__global__ void k_prep_w(const float* __restrict__ W_gat, const float* __restrict__ attn_l,
                         const float* __restrict__ attn_r, const float* __restrict__ gate_m_W,
                         const float* __restrict__ merge_W, const float* __restrict__ gate_fn_W)
{
    int n = blockIdx.x, k = threadIdx.x;
    float v = 0.f;
    if (n < 256)      v = W_gat[k * 256 + n];
    else if (n < 320) v = gate_m_W[k * 64 + (n - 256)];
    else if (n < 384) v = merge_W[k * 64 + (n - 320)];
    else if (n < 388) v = gate_fn_W[k * 4 + (n - 384)];
    else if (n < 392) v = gate_fn_W[(320 + k) * 4 + (n - 388)];
    else if (n < 396) {
        int h = n - 392; float s = 0.f;
        for (int o = 0; o < 64; o++) s += W_gat[k * 256 + h * 64 + o] * attn_l[h * 64 + o];
        v = s;
    } else if (n < 400) {
        int h = n - 396; float s = 0.f;
        for (int o = 0; o < 64; o++) s += W_gat[k * 256 + h * 64 + o] * attn_r[h * 64 + o];
        v = s;
    }
    __nv_bfloat16 hi = __float2bfloat16(v);
    g_wcat_hi[n * 256 + k] = __bfloat16_as_ushort(hi);
    g_wcat_lo[n * 256 + k] = __bfloat16_as_ushort(__float2bfloat16(v - __bfloat162float(hi)));
}

// ---------------- pipelined HMMA GEMM ----------------
#define STAGE 36864
#define GEMM_SMEM (2 * STAGE)

__global__ __launch_bounds__(256, 1) void k_gemm_mma(
    const float* __restrict__ gate_m_b, const float* __restrict__ merge_b,
    float* __restrict__ out)
{
    extern __shared__ __align__(16) char sm[];
    uint32_t sb = smem_u32(sm);
    int tid = threadIdx.x, w = tid >> 5, lane = tid & 31;
    int r0 = blockIdx.x * 128;
    int nb = blockIdx.y * 256;
    int wm = (w & 1) * 64, wn = (w >> 1) * 64;

    // preload addressing
    int arow = tid >> 1, akg = tid & 1;
    int agr = r0 + arow;
    uint32_t aok = (agr < N_NODES) ? 16u : 0u;
    if (agr >= N_NODES) agr = 0;
    const unsigned short* axh = g_x_hi + (size_t)agr * 256 + akg * 8;
    const unsigned short* axl = g_x_lo + (size_t)agr * 256 + akg * 8;
    uint32_t adst = arow * 48 + akg * 16;

    float acc[4][8][4];
    #pragma unroll
    for (int a = 0; a < 4; a++)
        #pragma unroll
        for (int b = 0; b < 8; b++)
            #pragma unroll
            for (int c = 0; c < 4; c++) acc[a][b][c] = 0.f;

    // ---- preload chunk 0
    {
        uint32_t base = sb;
        cpa16(base + adst, axh, aok);
        cpa16(base + 6144 + adst, axl, aok);
        #pragma unroll
        for (int i = 0; i < 2; i++) {
            int q = tid + i * 256;
            int row = q >> 1, kg = q & 1;
            uint32_t d = base + 12288 + row * 48 + kg * 16;
            cpa16(d, g_wcat_hi + (size_t)(nb + row) * 256 + kg * 8, 16);
            cpa16(d + 12288, g_wcat_lo + (size_t)(nb + row) * 256 + kg * 8, 16);
        }
        CPA_COMMIT();
    }

    for (int ch = 0; ch < 16; ch++) {
        if (ch < 15) {
            int k0 = (ch + 1) * 16;
            uint32_t base = sb + ((ch + 1) & 1) * STAGE;
            cpa16(base + adst, axh + k0, aok);
            cpa16(base + 6144 + adst, axl + k0, aok);
            #pragma unroll
            for (int i = 0; i < 2; i++) {
                int q = tid + i * 256;
                int row = q >> 1, kg = q & 1;
                uint32_t d = base + 12288 + row * 48 + kg * 16;
                cpa16(d, g_wcat_hi + (size_t)(nb + row) * 256 + k0 + kg * 8, 16);
                cpa16(d + 12288, g_wcat_lo + (size_t)(nb + row) * 256 + k0 + kg * 8, 16);
            }
            CPA_COMMIT();
            CPA_WAIT1();
        } else {
            CPA_WAIT0();
        }
        __syncthreads();

        uint32_t base = sb + (ch & 1) * STAGE;
        uint32_t aH[4][4], aL[4][4], bf[4][4];
        int ar = wm + (lane & 7) + ((lane & 8) ? 8 : 0);
        int ac = ((lane & 16) ? 16 : 0);
        #pragma unroll
        for (int mt = 0; mt < 4; mt++) {
            ldsm4(aH[mt], base + (ar + mt * 16) * 48 + ac);
            ldsm4(aL[mt], base + 6144 + (ar + mt * 16) * 48 + ac);
        }
        int br = wn + (lane & 7) + ((lane & 16) ? 8 : 0);
        int bc = ((lane & 8) ? 16 : 0);
        #pragma unroll
        for (int nt = 0; nt < 4; nt++)
            ldsm4(bf[nt], base + 12288 + (br + nt * 16) * 48 + bc);
        #pragma unroll
        for (int mt = 0; mt < 4; mt++)
            #pragma unroll
            for (int nt = 0; nt < 4; nt++) {
                mma16816(acc[mt][nt * 2],     aH[mt], &bf[nt][0]);
                mma16816(acc[mt][nt * 2 + 1], aH[mt], &bf[nt][2]);
                mma16816(acc[mt][nt * 2],     aL[mt], &bf[nt][0]);
                mma16816(acc[mt][nt * 2 + 1], aL[mt], &bf[nt][2]);
            }
        #pragma unroll
        for (int nt = 0; nt < 4; nt++)
            ldsm4(bf[nt], base + 24576 + (br + nt * 16) * 48 + bc);
        #pragma unroll
        for (int mt = 0; mt < 4; mt++)
            #pragma unroll
            for (int nt = 0; nt < 4; nt++) {
                mma16816(acc[mt][nt * 2],     aH[mt], &bf[nt][0]);
                mma16816(acc[mt][nt * 2 + 1], aH[mt], &bf[nt][2]);
            }
        __syncthreads();
    }

    // epilogue
    int gcbase = nb + wn;
    #pragma unroll
    for (int nt = 0; nt < 8; nt++) {
        int gc = gcbase + nt * 8 + 2 * (lane & 3);
        if (gc >= 400) continue;
        float b0 = 0.f, b1 = 0.f;
        if (gc >= 256 && gc < 320) { b0 = gate_m_b[gc - 256]; b1 = gate_m_b[gc - 255]; }
        else if (gc >= 320 && gc < 384) { b0 = merge_b[gc - 320]; b1 = merge_b[gc - 319]; }
        #pragma unroll
        for (int mt = 0; mt < 4; mt++) {
            int row0 = r0 + wm + mt * 16 + (lane >> 2);
            #pragma unroll
            for (int h = 0; h < 2; h++) {
                int row = row0 + h * 8;
                if (row >= N_NODES) continue;
                float v0 = acc[mt][nt][h * 2] + b0;
                float v1 = acc[mt][nt][h * 2 + 1] + b1;
                if (gc < 256)
                    ((uint32_t*)g_featb)[(size_t)row * 128 + (gc >> 1)] = packbf(v0, v1);
                else if (gc < 320)
                    ((uint32_t*)g_zb)[row * 32 + ((gc - 256) >> 1)] = packbf(v0, v1);
                else if (gc < 384)
                    *(float2*)(out + (size_t)row * 64 + (gc - 320)) = make_float2(v0, v1);
                else {
                    int cc = gc - 384;
                    float* bp = cc < 4 ? (float*)g_xc : cc < 8 ? (float*)g_px
                              : cc < 12 ? (float*)g_el : (float*)g_er;
                    *(float2*)(bp + (size_t)row * 4 + (cc & 3)) = make_float2(v0, v1);
                }
            }
        }
    }
}

// ---------------- fused aggregation + gate + merge2 ----------------
__global__ __launch_bounds__(256) void k_agg(
    const float* __restrict__ gate_fn_W, const float* __restrict__ gate_fn_b,
    const float* __restrict__ W2, float* __restrict__ out)
{
    __shared__ float4 s_wm[64];
    __shared__ float  s_W2[64 * 64];
    __shared__ float  s_gat[8][64];
    __shared__ float4 s_gb;
    int tid = threadIdx.x;
    if (tid < 64) s_wm[tid] = ((const float4*)gate_fn_W)[256 + tid];
    if (tid == 64) s_gb = *(const float4*)gate_fn_b;
    #pragma unroll
    for (int i = 0; i < 16; i++) s_W2[tid + i * 256] = W2[tid + i * 256];
    __syncthreads();

    int lane = tid & 31, w = tid >> 5;
    int n = blockIdx.x * 8 + w;
    if (n >= N_NODES) return;

    int beg = g_off[n], end = g_off[n + 1];
    int deg = end - beg;
    if (deg == 0) return;      // gated = 0 -> no merge contribution

    const int h = lane >> 3;
    float4 er4 = g_er[n];
    float er_h = sel4(er4, h);

    // pass 1: per-head max (lane-strided over edges)
    float4 m4 = make_float4(-1e30f, -1e30f, -1e30f, -1e30f);
    for (int j = beg + lane; j < end; j += 32) {
        int s = g_srcs[j];
        float4 el4 = g_el[s];
        m4.x = fmaxf(m4.x, lrelu(el4.x + er4.x));
        m4.y = fmaxf(m4.y, lrelu(el4.y + er4.y));
        m4.z = fmaxf(m4.z, lrelu(el4.z + er4.z));
        m4.w = fmaxf(m4.w, lrelu(el4.w + er4.w));
    }
    #pragma unroll
    for (int d = 16; d; d >>= 1) {
        m4.x = fmaxf(m4.x, __shfl_xor_sync(0xffffffffu, m4.x, d));
        m4.y = fmaxf(m4.y, __shfl_xor_sync(0xffffffffu, m4.y, d));
        m4.z = fmaxf(m4.z, __shfl_xor_sync(0xffffffffu, m4.z, d));
        m4.w = fmaxf(m4.w, __shfl_xor_sync(0xffffffffu, m4.w, d));
    }
    float m_h = sel4(m4, h);

    // pass 2: every lane walks all edges; lane owns feat cols 8l..8l+7 (single head)
    float facc[8];
    #pragma unroll
    for (int k = 0; k < 8; k++) facc[k] = 0.f;
    float sH = 0.f, pxs = 0.f;
    float mzx = -1e30f, mzy = -1e30f;
    const uint32_t* zb = (const uint32_t*)g_zb;
    const uint4* fb = (const uint4*)g_featb;

    int sj = g_srcs[beg];
    for (int j = beg; j < end; j++) {
        int s = sj;
        if (j + 1 < end) sj = g_srcs[j + 1];
        float4 el4 = g_el[s];
        float e = lrelu(sel4(el4, h) + er_h);
        float ex = __expf(e - m_h);
        sH += ex;
        pxs += ((const float*)(g_px + s))[h];
        uint32_t zr = zb[s * 32 + lane];
        mzx = fmaxf(mzx, bflo(zr)); mzy = fmaxf(mzy, bfhi(zr));
        uint4 fv = fb[(size_t)s * 32 + lane];
        facc[0] = fmaf(bflo(fv.x), ex, facc[0]);
        facc[1] = fmaf(bfhi(fv.x), ex, facc[1]);
        facc[2] = fmaf(bflo(fv.y), ex, facc[2]);
        facc[3] = fmaf(bfhi(fv.y), ex, facc[3]);
        facc[4] = fmaf(bflo(fv.z), ex, facc[4]);
        facc[5] = fmaf(bfhi(fv.z), ex, facc[5]);
        facc[6] = fmaf(bflo(fv.w), ex, facc[6]);
        facc[7] = fmaf(bfhi(fv.w), ex, facc[7]);
    }

    // gate logits (z cols 2l, 2l+1 per lane; butterfly over lanes)
    float4 wA = s_wm[2 * lane], wB = s_wm[2 * lane + 1];
    float4 gl;
    gl.x = mzx * wA.x + mzy * wB.x;
    gl.y = mzx * wA.y + mzy * wB.y;
    gl.z = mzx * wA.z + mzy * wB.z;
    gl.w = mzx * wA.w + mzy * wB.w;
    #pragma unroll
    for (int d = 16; d; d >>= 1) {
        gl.x += __shfl_xor_sync(0xffffffffu, gl.x, d);
        gl.y += __shfl_xor_sync(0xffffffffu, gl.y, d);
        gl.z += __shfl_xor_sync(0xffffffffu, gl.z, d);
        gl.w += __shfl_xor_sync(0xffffffffu, gl.w, d);
    }
    float invdeg = 1.f / (float)deg;
    float t = sel4(g_xc[n], h) + pxs * invdeg + sel4(gl, h) + sel4(s_gb, h);
    float gate = 1.f / (1.f + __expf(-t));
    float c = gate / fmaxf(sH, 1e-16f);

    // scale + sum over heads (lanes l, l^8, l^16, l^24 share output cols)
    float r[8];
    #pragma unroll
    for (int k = 0; k < 8; k++) {
        float v = facc[k] * c;
        v += __shfl_xor_sync(0xffffffffu, v, 8);
        v += __shfl_xor_sync(0xffffffffu, v, 16);
        r[k] = v * 0.25f;
    }
    if (lane < 8) {
        #pragma unroll
        for (int k = 0; k < 8; k++) s_gat[w][8 * lane + k] = r[k];
    }
    __syncwarp();

    // merge2: out[n][2l..2l+1] += gated @ W2
    float o0 = 0.f, o1 = 0.f;
    #pragma unroll 4
    for (int k = 0; k < 64; k++) {
        float g = s_gat[w][k];
        float2 w2 = ((const float2*)s_W2)[k * 32 + lane];
        o0 = fmaf(g, w2.x, o0);
        o1 = fmaf(g, w2.y, o1);
    }
    float2* op = (float2*)(out + (size_t)n * 64) + lane;
    float2 o = *op;
    o.x += o0; o.y += o1;
    *op = o;
}

// ---------------- launch ----------------
extern "C" void kernel_launch(void* const* d_in, const int* in_sizes, int n_in,
                              void* d_out, int out_size)
{
    const float* x         = (const float*)d_in[0];
    const int*   src       = (const int*)d_in[1];
    const int*   dst       = (const int*)d_in[2];
    const float* W_gat     = (const float*)d_in[3];
    const float* attn_l    = (const float*)d_in[4];
    const float* attn_r    = (const float*)d_in[5];
    const float* gate_m_W  = (const float*)d_in[6];
    const float* gate_m_b  = (const float*)d_in[7];
    const float* gate_fn_W = (const float*)d_in[8];
    const float* gate_fn_b = (const float*)d_in[9];
    const float* merge_W   = (const float*)d_in[10];
    const float* merge_b   = (const float*)d_in[11];
    float* out = (float*)d_out;

    cudaFuncSetAttribute(k_gemm_mma, cudaFuncAttributeMaxDynamicSharedMemorySize, GEMM_SMEM);

    k_zero_deg<<<(N_NODES + 255) / 256, 256>>>();
    k_hist<<<(N_EDGES + 255) / 256, 256>>>(dst);
    k_scan<<<1, 1024>>>();
    k_scatter<<<(N_EDGES + 255) / 256, 256>>>(src, dst);

    k_split_x<<<(N_NODES * 64 + 255) / 256, 256>>>(x);
    k_prep_w<<<NCOLS, 256>>>(W_gat, attn_l, attn_r, gate_m_W, merge_W, gate_fn_W);
    k_gemm_mma<<<dim3((N_NODES + 127) / 128, 2), 256, GEMM_SMEM>>>(gate_m_b, merge_b, out);

    k_agg<<<(N_NODES + 7) / 8, 256>>>(gate_fn_W, gate_fn_b, merge_W + 256 * 64, out);
}

// round 5
// speedup vs baseline: 1.5223x; 1.0597x over previous
#include <cuda_runtime.h>
#include <cuda_bf16.h>
#include <cstdint>

#define N_NODES 50000
#define N_EDGES 800000
#define IN_DIM  256
#define NCOLS   512

// ---------------- scratch ----------------
__device__ unsigned short g_zb[N_NODES * 64];
__device__ unsigned short g_featb[(size_t)N_NODES * 256];
__device__ float4 g_el[N_NODES];
__device__ float4 g_er[N_NODES];
__device__ float4 g_xc[N_NODES];
__device__ float4 g_px[N_NODES];
__device__ int    g_deg[N_NODES];
__device__ int    g_off[N_NODES + 1];
__device__ int    g_cur[N_NODES];
__device__ int    g_srcs[N_EDGES];
__device__ unsigned int g_elmax[4];
__device__ unsigned short g_wcat_hi[NCOLS * IN_DIM];
__device__ unsigned short g_wcat_lo[NCOLS * IN_DIM];
__device__ unsigned short g_x_hi[(size_t)N_NODES * IN_DIM];
__device__ unsigned short g_x_lo[(size_t)N_NODES * IN_DIM];

__device__ __forceinline__ float lrelu(float v) { return v > 0.f ? v : 0.2f * v; }
__device__ __forceinline__ float sel4(float4 v, int h) {
    float r = v.x;
    r = (h == 1) ? v.y : r;
    r = (h == 2) ? v.z : r;
    r = (h == 3) ? v.w : r;
    return r;
}
__device__ __forceinline__ float bflo(uint32_t u) { return __uint_as_float(u << 16); }
__device__ __forceinline__ float bfhi(uint32_t u) { return __uint_as_float(u & 0xFFFF0000u); }
__device__ __forceinline__ uint32_t packbf(float a, float b) {
    return (uint32_t)__bfloat16_as_ushort(__float2bfloat16(a)) |
           ((uint32_t)__bfloat16_as_ushort(__float2bfloat16(b)) << 16);
}
// monotone float<->uint encoding for atomicMax on floats
__device__ __forceinline__ uint32_t fenc(float f) {
    uint32_t b = __float_as_uint(f);
    return (b & 0x80000000u) ? ~b : (b | 0x80000000u);
}
__device__ __forceinline__ float fdec(uint32_t u) {
    uint32_t b = (u & 0x80000000u) ? (u ^ 0x80000000u) : ~u;
    return __uint_as_float(b);
}

__device__ __forceinline__ uint32_t smem_u32(const void* p) {
    uint32_t a;
    asm("{ .reg .u64 t; cvta.to.shared.u64 t, %1; cvt.u32.u64 %0, t; }" : "=r"(a) : "l"(p));
    return a;
}
__device__ __forceinline__ void ldsm4(uint32_t* r, uint32_t addr) {
    asm volatile("ldmatrix.sync.aligned.m8n8.x4.shared.b16 {%0,%1,%2,%3}, [%4];"
        : "=r"(r[0]), "=r"(r[1]), "=r"(r[2]), "=r"(r[3]) : "r"(addr));
}
__device__ __forceinline__ void mma16816(float* c, const uint32_t* a, const uint32_t* b) {
    asm volatile("mma.sync.aligned.m16n8k16.row.col.f32.bf16.bf16.f32 "
        "{%0,%1,%2,%3}, {%4,%5,%6,%7}, {%8,%9}, {%0,%1,%2,%3};"
        : "+f"(c[0]), "+f"(c[1]), "+f"(c[2]), "+f"(c[3])
        : "r"(a[0]), "r"(a[1]), "r"(a[2]), "r"(a[3]), "r"(b[0]), "r"(b[1]));
}
__device__ __forceinline__ void cpa16(uint32_t dst, const void* src, uint32_t sz) {
    asm volatile("cp.async.cg.shared.global [%0], [%1], 16, %2;"
        :: "r"(dst), "l"(src), "r"(sz) : "memory");
}
#define CPA_COMMIT() asm volatile("cp.async.commit_group;" ::: "memory")
#define CPA_WAIT2()  asm volatile("cp.async.wait_group 2;" ::: "memory")

// ---------------- CSR build ----------------
__global__ void k_zero_deg() {
    int i = blockIdx.x * blockDim.x + threadIdx.x;
    if (i < N_NODES) g_deg[i] = 0;
    if (i < 4) g_elmax[i] = fenc(-1e30f);
}
__global__ void k_hist(const int* __restrict__ dst) {
    int e = blockIdx.x * blockDim.x + threadIdx.x;
    if (e < N_EDGES) atomicAdd(&g_deg[dst[e]], 1);
}
__global__ __launch_bounds__(1024) void k_scan() {
    __shared__ int wsum[32];
    int t = threadIdx.x, lane = t & 31, w = t >> 5;
    const int CH = (N_NODES + 1023) / 1024;
    int b = t * CH; if (b > N_NODES) b = N_NODES;
    int e = b + CH; if (e > N_NODES) e = N_NODES;
    int s = 0;
    for (int i = b; i < e; i++) s += g_deg[i];
    int v = s;
    #pragma unroll
    for (int d = 1; d < 32; d <<= 1) {
        int u = __shfl_up_sync(0xffffffffu, v, d);
        if (lane >= d) v += u;
    }
    if (lane == 31) wsum[w] = v;
    __syncthreads();
    if (w == 0) {
        int ws = wsum[lane];
        #pragma unroll
        for (int d = 1; d < 32; d <<= 1) {
            int u = __shfl_up_sync(0xffffffffu, ws, d);
            if (lane >= d) ws += u;
        }
        wsum[lane] = ws;
    }
    __syncthreads();
    int run = (w ? wsum[w - 1] : 0) + (v - s);
    for (int i = b; i < e; i++) {
        g_off[i] = run; g_cur[i] = run;
        run += g_deg[i];
    }
    if (b < N_NODES && e == N_NODES) g_off[N_NODES] = run;
}
__global__ void k_scatter(const int* __restrict__ src, const int* __restrict__ dst) {
    int e = blockIdx.x * blockDim.x + threadIdx.x;
    if (e < N_EDGES) {
        int p = atomicAdd(&g_cur[dst[e]], 1);
        g_srcs[p] = src[e];
    }
}

// ---------------- x split ----------------
__global__ void k_split_x(const float* __restrict__ x) {
    size_t idx = (size_t)blockIdx.x * blockDim.x + threadIdx.x;
    if (idx >= (size_t)N_NODES * 64) return;
    float4 v = ((const float4*)x)[idx];
    __nv_bfloat16 h0 = __float2bfloat16(v.x), h1 = __float2bfloat16(v.y);
    __nv_bfloat16 h2 = __float2bfloat16(v.z), h3 = __float2bfloat16(v.w);
    uint2 hh, ll;
    hh.x = (uint32_t)__bfloat16_as_ushort(h0) | ((uint32_t)__bfloat16_as_ushort(h1) << 16);
    hh.y = (uint32_t)__bfloat16_as_ushort(h2) | ((uint32_t)__bfloat16_as_ushort(h3) << 16);
    ll.x = packbf(v.x - __bfloat162float(h0), v.y - __bfloat162float(h1));
    ll.y = packbf(v.z - __bfloat162float(h2), v.w - __bfloat162float(h3));
    ((uint2*)g_x_hi)[idx] = hh;
    ((uint2*)g_x_lo)[idx] = ll;
}

// ---------------- weight concat ----------------
__global__ void k_prep_w(const float* __restrict__ W_gat, const float* __restrict__ attn_l,
                         const float* __restrict__ attn_r, const float* __restrict__ gate_m_W,
                         const float* __restrict__ merge_W, const float* __restrict__ gate_fn_W)
{
    int n = blockIdx.x, k = threadIdx.x;
    float v = 0.f;
    if (n < 256)      v = W_gat[k * 256 + n];
    else if (n < 320) v = gate_m_W[k * 64 + (n - 256)];
    else if (n < 384) v = merge_W[k * 64 + (n - 320)];
    else if (n < 388) v = gate_fn_W[k * 4 + (n - 384)];
    else if (n < 392) v = gate_fn_W[(320 + k) * 4 + (n - 388)];
    else if (n < 396) {
        int h = n - 392; float s = 0.f;
        for (int o = 0; o < 64; o++) s += W_gat[k * 256 + h * 64 + o] * attn_l[h * 64 + o];
        v = s;
    } else if (n < 400) {
        int h = n - 396; float s = 0.f;
        for (int o = 0; o < 64; o++) s += W_gat[k * 256 + h * 64 + o] * attn_r[h * 64 + o];
        v = s;
    }
    __nv_bfloat16 hi = __float2bfloat16(v);
    g_wcat_hi[n * 256 + k] = __bfloat16_as_ushort(hi);
    g_wcat_lo[n * 256 + k] = __bfloat16_as_ushort(__float2bfloat16(v - __bfloat162float(hi)));
}

// ---------------- pipelined HMMA GEMM: 4 stages, 1 sync/chunk ----------------
#define STAGE 36864
#define GEMM_SMEM (4 * STAGE)

__global__ __launch_bounds__(256, 1) void k_gemm_mma(
    const float* __restrict__ gate_m_b, const float* __restrict__ merge_b,
    float* __restrict__ out)
{
    extern __shared__ __align__(16) char sm[];
    uint32_t sb = smem_u32(sm);
    int tid = threadIdx.x, w = tid >> 5, lane = tid & 31;
    int r0 = blockIdx.x * 128;
    int nb = blockIdx.y * 256;
    int wm = (w & 1) * 64, wn = (w >> 1) * 64;

    int arow = tid >> 1, akg = tid & 1;
    int agr = r0 + arow;
    uint32_t aok = (agr < N_NODES) ? 16u : 0u;
    if (agr >= N_NODES) agr = 0;
    const unsigned short* axh = g_x_hi + (size_t)agr * 256 + akg * 8;
    const unsigned short* axl = g_x_lo + (size_t)agr * 256 + akg * 8;
    uint32_t adst = arow * 48 + akg * 16;

    auto load_chunk = [&](int ch, uint32_t base) {
        int k0 = ch * 16;
        cpa16(base + adst, axh + k0, aok);
        cpa16(base + 6144 + adst, axl + k0, aok);
        #pragma unroll
        for (int i = 0; i < 2; i++) {
            int q = tid + i * 256;
            int row = q >> 1, kg = q & 1;
            uint32_t d = base + 12288 + row * 48 + kg * 16;
            cpa16(d, g_wcat_hi + (size_t)(nb + row) * 256 + k0 + kg * 8, 16);
            cpa16(d + 12288, g_wcat_lo + (size_t)(nb + row) * 256 + k0 + kg * 8, 16);
        }
    };

    float acc[4][8][4];
    #pragma unroll
    for (int a = 0; a < 4; a++)
        #pragma unroll
        for (int b = 0; b < 8; b++)
            #pragma unroll
            for (int c = 0; c < 4; c++) acc[a][b][c] = 0.f;

    #pragma unroll
    for (int p = 0; p < 3; p++) { load_chunk(p, sb + p * STAGE); CPA_COMMIT(); }

    for (int ch = 0; ch < 16; ch++) {
        CPA_WAIT2();
        __syncthreads();
        uint32_t base = sb + (ch & 3) * STAGE;
        uint32_t aH[4][4], aL[4][4], bf[4][4];
        int ar = wm + (lane & 7) + ((lane & 8) ? 8 : 0);
        int ac = ((lane & 16) ? 16 : 0);
        #pragma unroll
        for (int mt = 0; mt < 4; mt++) {
            ldsm4(aH[mt], base + (ar + mt * 16) * 48 + ac);
            ldsm4(aL[mt], base + 6144 + (ar + mt * 16) * 48 + ac);
        }
        int br = wn + (lane & 7) + ((lane & 16) ? 8 : 0);
        int bc = ((lane & 8) ? 16 : 0);
        #pragma unroll
        for (int nt = 0; nt < 4; nt++)
            ldsm4(bf[nt], base + 12288 + (br + nt * 16) * 48 + bc);
        #pragma unroll
        for (int mt = 0; mt < 4; mt++)
            #pragma unroll
            for (int nt = 0; nt < 4; nt++) {
                mma16816(acc[mt][nt * 2],     aH[mt], &bf[nt][0]);
                mma16816(acc[mt][nt * 2 + 1], aH[mt], &bf[nt][2]);
                mma16816(acc[mt][nt * 2],     aL[mt], &bf[nt][0]);
                mma16816(acc[mt][nt * 2 + 1], aL[mt], &bf[nt][2]);
            }
        #pragma unroll
        for (int nt = 0; nt < 4; nt++)
            ldsm4(bf[nt], base + 24576 + (br + nt * 16) * 48 + bc);
        #pragma unroll
        for (int mt = 0; mt < 4; mt++)
            #pragma unroll
            for (int nt = 0; nt < 4; nt++) {
                mma16816(acc[mt][nt * 2],     aH[mt], &bf[nt][0]);
                mma16816(acc[mt][nt * 2 + 1], aH[mt], &bf[nt][2]);
            }
        if (ch + 3 < 16) load_chunk(ch + 3, sb + ((ch + 3) & 3) * STAGE);
        CPA_COMMIT();
    }

    // epilogue
    int gcbase = nb + wn;
    #pragma unroll
    for (int nt = 0; nt < 8; nt++) {
        int gc = gcbase + nt * 8 + 2 * (lane & 3);
        if (gc >= 400) continue;
        float b0 = 0.f, b1 = 0.f;
        if (gc >= 256 && gc < 320) { b0 = gate_m_b[gc - 256]; b1 = gate_m_b[gc - 255]; }
        else if (gc >= 320 && gc < 384) { b0 = merge_b[gc - 320]; b1 = merge_b[gc - 319]; }
        #pragma unroll
        for (int mt = 0; mt < 4; mt++) {
            int row0 = r0 + wm + mt * 16 + (lane >> 2);
            #pragma unroll
            for (int h = 0; h < 2; h++) {
                int row = row0 + h * 8;
                if (row >= N_NODES) continue;
                float v0 = acc[mt][nt][h * 2] + b0;
                float v1 = acc[mt][nt][h * 2 + 1] + b1;
                if (gc < 256)
                    ((uint32_t*)g_featb)[(size_t)row * 128 + (gc >> 1)] = packbf(v0, v1);
                else if (gc < 320)
                    ((uint32_t*)g_zb)[row * 32 + ((gc - 256) >> 1)] = packbf(v0, v1);
                else if (gc < 384)
                    *(float2*)(out + (size_t)row * 64 + (gc - 320)) = make_float2(v0, v1);
                else {
                    int cc = gc - 384;
                    float* bp = cc < 4 ? (float*)g_xc : cc < 8 ? (float*)g_px
                              : cc < 12 ? (float*)g_el : (float*)g_er;
                    *(float2*)(bp + (size_t)row * 4 + (cc & 3)) = make_float2(v0, v1);
                }
            }
        }
    }
}

// ---------------- global per-head max of el ----------------
__global__ __launch_bounds__(256) void k_elmax() {
    __shared__ uint32_t red[256];
    int t = threadIdx.x;
    int h = t & 3;
    const float* elf = (const float*)g_el;
    uint32_t local = fenc(-1e30f);
    for (int i = blockIdx.x * 64 + (t >> 2); i < N_NODES; i += gridDim.x * 64)
        local = max(local, fenc(elf[4 * i + h]));
    red[t] = local;
    __syncthreads();
    #pragma unroll
    for (int off = 128; off >= 4; off >>= 1) {
        if (t < off) red[t] = max(red[t], red[t + off]);
        __syncthreads();
    }
    if (t < 4) atomicMax(&g_elmax[t], red[t]);
}

// ---------------- fused aggregation + gate + merge2 ----------------
__global__ __launch_bounds__(256) void k_agg(
    const float* __restrict__ gate_fn_W, const float* __restrict__ gate_fn_b,
    const float* __restrict__ W2, float* __restrict__ out)
{
    __shared__ float4 s_wm[64];
    __shared__ float  s_W2[64 * 64];
    __shared__ float  s_gat[8][64];
    __shared__ float4 s_gb;
    int tid = threadIdx.x;
    if (tid < 64) s_wm[tid] = ((const float4*)gate_fn_W)[256 + tid];
    if (tid == 64) s_gb = *(const float4*)gate_fn_b;
    #pragma unroll
    for (int i = 0; i < 16; i++) s_W2[tid + i * 256] = W2[tid + i * 256];
    __syncthreads();

    int lane = tid & 31, w = tid >> 5;
    int n = blockIdx.x * 8 + w;
    if (n >= N_NODES) return;

    int beg = g_off[n], end = g_off[n + 1];
    int deg = end - beg;
    if (deg == 0) return;

    const int h = lane >> 3;
    const float* elf = (const float*)g_el;
    const float* pxf = (const float*)g_px;
    const uint32_t* zb = (const uint32_t*)g_zb;
    const uint4* fb = (const uint4*)g_featb;

    float er_h = ((const float*)(g_er + n))[h];
    float m_h = lrelu(fdec(g_elmax[h]) + er_h);   // upper bound on e for this node/head

    float facc[8];
    #pragma unroll
    for (int k = 0; k < 8; k++) facc[k] = 0.f;
    float sH = 0.f, pxs = 0.f;
    float mzx = -1e30f, mzy = -1e30f;

    int j = beg;
    for (; j + 4 <= end; j += 4) {
        int s0 = g_srcs[j], s1 = g_srcs[j + 1], s2 = g_srcs[j + 2], s3 = g_srcs[j + 3];
        float el0 = elf[4 * s0 + h], el1 = elf[4 * s1 + h];
        float el2 = elf[4 * s2 + h], el3 = elf[4 * s3 + h];
        float p0 = pxf[4 * s0 + h], p1 = pxf[4 * s1 + h];
        float p2 = pxf[4 * s2 + h], p3 = pxf[4 * s3 + h];
        uint32_t z0 = zb[s0 * 32 + lane], z1 = zb[s1 * 32 + lane];
        uint32_t z2 = zb[s2 * 32 + lane], z3 = zb[s3 * 32 + lane];
        uint4 f0 = fb[(size_t)s0 * 32 + lane], f1 = fb[(size_t)s1 * 32 + lane];
        uint4 f2 = fb[(size_t)s2 * 32 + lane], f3 = fb[(size_t)s3 * 32 + lane];

        float ex0 = __expf(lrelu(el0 + er_h) - m_h);
        float ex1 = __expf(lrelu(el1 + er_h) - m_h);
        float ex2 = __expf(lrelu(el2 + er_h) - m_h);
        float ex3 = __expf(lrelu(el3 + er_h) - m_h);
        sH += (ex0 + ex1) + (ex2 + ex3);
        pxs += (p0 + p1) + (p2 + p3);
        mzx = fmaxf(fmaxf(mzx, bflo(z0)), fmaxf(bflo(z1), fmaxf(bflo(z2), bflo(z3))));
        mzy = fmaxf(fmaxf(mzy, bfhi(z0)), fmaxf(bfhi(z1), fmaxf(bfhi(z2), bfhi(z3))));

        facc[0] = fmaf(bflo(f0.x), ex0, fmaf(bflo(f1.x), ex1, fmaf(bflo(f2.x), ex2, fmaf(bflo(f3.x), ex3, facc[0]))));
        facc[1] = fmaf(bfhi(f0.x), ex0, fmaf(bfhi(f1.x), ex1, fmaf(bfhi(f2.x), ex2, fmaf(bfhi(f3.x), ex3, facc[1]))));
        facc[2] = fmaf(bflo(f0.y), ex0, fmaf(bflo(f1.y), ex1, fmaf(bflo(f2.y), ex2, fmaf(bflo(f3.y), ex3, facc[2]))));
        facc[3] = fmaf(bfhi(f0.y), ex0, fmaf(bfhi(f1.y), ex1, fmaf(bfhi(f2.y), ex2, fmaf(bfhi(f3.y), ex3, facc[3]))));
        facc[4] = fmaf(bflo(f0.z), ex0, fmaf(bflo(f1.z), ex1, fmaf(bflo(f2.z), ex2, fmaf(bflo(f3.z), ex3, facc[4]))));
        facc[5] = fmaf(bfhi(f0.z), ex0, fmaf(bfhi(f1.z), ex1, fmaf(bfhi(f2.z), ex2, fmaf(bfhi(f3.z), ex3, facc[5]))));
        facc[6] = fmaf(bflo(f0.w), ex0, fmaf(bflo(f1.w), ex1, fmaf(bflo(f2.w), ex2, fmaf(bflo(f3.w), ex3, facc[6]))));
        facc[7] = fmaf(bfhi(f0.w), ex0, fmaf(bfhi(f1.w), ex1, fmaf(bfhi(f2.w), ex2, fmaf(bfhi(f3.w), ex3, facc[7]))));
    }
    for (; j < end; j++) {
        int s = g_srcs[j];
        float ex = __expf(lrelu(elf[4 * s + h] + er_h) - m_h);
        sH += ex;
        pxs += pxf[4 * s + h];
        uint32_t zr = zb[s * 32 + lane];
        mzx = fmaxf(mzx, bflo(zr)); mzy = fmaxf(mzy, bfhi(zr));
        uint4 fv = fb[(size_t)s * 32 + lane];
        facc[0] = fmaf(bflo(fv.x), ex, facc[0]);
        facc[1] = fmaf(bfhi(fv.x), ex, facc[1]);
        facc[2] = fmaf(bflo(fv.y), ex, facc[2]);
        facc[3] = fmaf(bfhi(fv.y), ex, facc[3]);
        facc[4] = fmaf(bflo(fv.z), ex, facc[4]);
        facc[5] = fmaf(bfhi(fv.z), ex, facc[5]);
        facc[6] = fmaf(bflo(fv.w), ex, facc[6]);
        facc[7] = fmaf(bfhi(fv.w), ex, facc[7]);
    }

    // gate logits (z cols 2l, 2l+1 per lane; butterfly over lanes)
    float4 wA = s_wm[2 * lane], wB = s_wm[2 * lane + 1];
    float4 gl;
    gl.x = mzx * wA.x + mzy * wB.x;
    gl.y = mzx * wA.y + mzy * wB.y;
    gl.z = mzx * wA.z + mzy * wB.z;
    gl.w = mzx * wA.w + mzy * wB.w;
    #pragma unroll
    for (int d = 16; d; d >>= 1) {
        gl.x += __shfl_xor_sync(0xffffffffu, gl.x, d);
        gl.y += __shfl_xor_sync(0xffffffffu, gl.y, d);
        gl.z += __shfl_xor_sync(0xffffffffu, gl.z, d);
        gl.w += __shfl_xor_sync(0xffffffffu, gl.w, d);
    }
    float invdeg = 1.f / (float)deg;
    float t = sel4(g_xc[n], h) + pxs * invdeg + sel4(gl, h) + sel4(s_gb, h);
    float gate = 1.f / (1.f + __expf(-t));
    float c = gate / fmaxf(sH, 1e-16f);

    float r[8];
    #pragma unroll
    for (int k = 0; k < 8; k++) {
        float v = facc[k] * c;
        v += __shfl_xor_sync(0xffffffffu, v, 8);
        v += __shfl_xor_sync(0xffffffffu, v, 16);
        r[k] = v * 0.25f;
    }
    if (lane < 8) {
        #pragma unroll
        for (int k = 0; k < 8; k++) s_gat[w][8 * lane + k] = r[k];
    }
    __syncwarp();

    float o0 = 0.f, o1 = 0.f;
    #pragma unroll 4
    for (int k = 0; k < 64; k++) {
        float g = s_gat[w][k];
        float2 w2 = ((const float2*)s_W2)[k * 32 + lane];
        o0 = fmaf(g, w2.x, o0);
        o1 = fmaf(g, w2.y, o1);
    }
    float2* op = (float2*)(out + (size_t)n * 64) + lane;
    float2 o = *op;
    o.x += o0; o.y += o1;
    *op = o;
}

// ---------------- launch ----------------
extern "C" void kernel_launch(void* const* d_in, const int* in_sizes, int n_in,
                              void* d_out, int out_size)
{
    const float* x         = (const float*)d_in[0];
    const int*   src       = (const int*)d_in[1];
    const int*   dst       = (const int*)d_in[2];
    const float* W_gat     = (const float*)d_in[3];
    const float* attn_l    = (const float*)d_in[4];
    const float* attn_r    = (const float*)d_in[5];
    const float* gate_m_W  = (const float*)d_in[6];
    const float* gate_m_b  = (const float*)d_in[7];
    const float* gate_fn_W = (const float*)d_in[8];
    const float* gate_fn_b = (const float*)d_in[9];
    const float* merge_W   = (const float*)d_in[10];
    const float* merge_b   = (const float*)d_in[11];
    float* out = (float*)d_out;

    cudaFuncSetAttribute(k_gemm_mma, cudaFuncAttributeMaxDynamicSharedMemorySize, GEMM_SMEM);

    k_zero_deg<<<(N_NODES + 255) / 256, 256>>>();
    k_hist<<<(N_EDGES + 255) / 256, 256>>>(dst);
    k_scan<<<1, 1024>>>();
    k_scatter<<<(N_EDGES + 255) / 256, 256>>>(src, dst);

    k_split_x<<<(N_NODES * 64 + 255) / 256, 256>>>(x);
    k_prep_w<<<NCOLS, 256>>>(W_gat, attn_l, attn_r, gate_m_W, merge_W, gate_fn_W);
    k_gemm_mma<<<dim3((N_NODES + 127) / 128, 2), 256, GEMM_SMEM>>>(gate_m_b, merge_b, out);

    k_elmax<<<128, 256>>>();
    k_agg<<<(N_NODES + 7) / 8, 256>>>(gate_fn_W, gate_fn_b, merge_W + 256 * 64, out);
}

// round 6
// speedup vs baseline: 1.9714x; 1.2950x over previous
#include <cuda_runtime.h>
#include <cuda_bf16.h>
#include <cstdint>

#define N_NODES 50000
#define N_EDGES 800000
#define IN_DIM  256
#define NCOLS   512

// ---------------- scratch ----------------
__device__ unsigned short g_zb[N_NODES * 64];
__device__ unsigned short g_featb[(size_t)N_NODES * 256];
__device__ float4 g_el[N_NODES];
__device__ float4 g_er[N_NODES];
__device__ float4 g_xc[N_NODES];
__device__ float4 g_px[N_NODES];
__device__ int    g_deg[N_NODES];
__device__ int    g_off[N_NODES + 1];
__device__ int    g_cur[N_NODES];
__device__ int    g_srcs[N_EDGES];
__device__ unsigned int g_elmax[4];
__device__ unsigned short g_wcat_hi[NCOLS * IN_DIM];
__device__ unsigned short g_wcat_lo[NCOLS * IN_DIM];
__device__ unsigned short g_x_hi[(size_t)N_NODES * IN_DIM];
__device__ unsigned short g_x_lo[(size_t)N_NODES * IN_DIM];

__device__ __forceinline__ float lrelu(float v) { return v > 0.f ? v : 0.2f * v; }
__device__ __forceinline__ float sel4(float4 v, int h) {
    float r = v.x;
    r = (h == 1) ? v.y : r;
    r = (h == 2) ? v.z : r;
    r = (h == 3) ? v.w : r;
    return r;
}
__device__ __forceinline__ float bflo(uint32_t u) { return __uint_as_float(u << 16); }
__device__ __forceinline__ float bfhi(uint32_t u) { return __uint_as_float(u & 0xFFFF0000u); }
__device__ __forceinline__ uint32_t packbf(float a, float b) {
    return (uint32_t)__bfloat16_as_ushort(__float2bfloat16(a)) |
           ((uint32_t)__bfloat16_as_ushort(__float2bfloat16(b)) << 16);
}
__device__ __forceinline__ uint32_t fenc(float f) {
    uint32_t b = __float_as_uint(f);
    return (b & 0x80000000u) ? ~b : (b | 0x80000000u);
}
__device__ __forceinline__ float fdec(uint32_t u) {
    uint32_t b = (u & 0x80000000u) ? (u ^ 0x80000000u) : ~u;
    return __uint_as_float(b);
}

__device__ __forceinline__ uint32_t smem_u32(const void* p) {
    uint32_t a;
    asm("{ .reg .u64 t; cvta.to.shared.u64 t, %1; cvt.u32.u64 %0, t; }" : "=r"(a) : "l"(p));
    return a;
}
__device__ __forceinline__ void ldsm4(uint32_t* r, uint32_t addr) {
    asm volatile("ldmatrix.sync.aligned.m8n8.x4.shared.b16 {%0,%1,%2,%3}, [%4];"
        : "=r"(r[0]), "=r"(r[1]), "=r"(r[2]), "=r"(r[3]) : "r"(addr));
}
__device__ __forceinline__ void mma16816(float* c, const uint32_t* a, const uint32_t* b) {
    asm volatile("mma.sync.aligned.m16n8k16.row.col.f32.bf16.bf16.f32 "
        "{%0,%1,%2,%3}, {%4,%5,%6,%7}, {%8,%9}, {%0,%1,%2,%3};"
        : "+f"(c[0]), "+f"(c[1]), "+f"(c[2]), "+f"(c[3])
        : "r"(a[0]), "r"(a[1]), "r"(a[2]), "r"(a[3]), "r"(b[0]), "r"(b[1]));
}
__device__ __forceinline__ void cpa16(uint32_t dst, const void* src, uint32_t sz) {
    asm volatile("cp.async.cg.shared.global [%0], [%1], 16, %2;"
        :: "r"(dst), "l"(src), "r"(sz) : "memory");
}
#define CPA_COMMIT() asm volatile("cp.async.commit_group;" ::: "memory")
#define CPA_WAIT2()  asm volatile("cp.async.wait_group 2;" ::: "memory")

// ---------------- CSR build ----------------
__global__ void k_zero_deg() {
    int i = blockIdx.x * blockDim.x + threadIdx.x;
    if (i < N_NODES) g_deg[i] = 0;
}
__global__ void k_hist(const int* __restrict__ dst) {
    int e = blockIdx.x * blockDim.x + threadIdx.x;
    if (e < N_EDGES) atomicAdd(&g_deg[dst[e]], 1);
}
__global__ __launch_bounds__(1024) void k_scan() {
    __shared__ int wsum[32];
    int t = threadIdx.x, lane = t & 31, w = t >> 5;
    const int CH = (N_NODES + 1023) / 1024;
    int b = t * CH; if (b > N_NODES) b = N_NODES;
    int e = b + CH; if (e > N_NODES) e = N_NODES;
    int s = 0;
    for (int i = b; i < e; i++) s += g_deg[i];
    int v = s;
    #pragma unroll
    for (int d = 1; d < 32; d <<= 1) {
        int u = __shfl_up_sync(0xffffffffu, v, d);
        if (lane >= d) v += u;
    }
    if (lane == 31) wsum[w] = v;
    __syncthreads();
    if (w == 0) {
        int ws = wsum[lane];
        #pragma unroll
        for (int d = 1; d < 32; d <<= 1) {
            int u = __shfl_up_sync(0xffffffffu, ws, d);
            if (lane >= d) ws += u;
        }
        wsum[lane] = ws;
    }
    __syncthreads();
    int run = (w ? wsum[w - 1] : 0) + (v - s);
    for (int i = b; i < e; i++) {
        g_off[i] = run; g_cur[i] = run;
        run += g_deg[i];
    }
    if (b < N_NODES && e == N_NODES) g_off[N_NODES] = run;
}
__global__ void k_scatter(const int* __restrict__ src, const int* __restrict__ dst) {
    int e = blockIdx.x * blockDim.x + threadIdx.x;
    if (e < N_EDGES) {
        int p = atomicAdd(&g_cur[dst[e]], 1);
        g_srcs[p] = src[e];
    }
}

// ---------------- x split ----------------
__global__ void k_split_x(const float* __restrict__ x) {
    size_t idx = (size_t)blockIdx.x * blockDim.x + threadIdx.x;
    if (idx >= (size_t)N_NODES * 64) return;
    float4 v = ((const float4*)x)[idx];
    __nv_bfloat16 h0 = __float2bfloat16(v.x), h1 = __float2bfloat16(v.y);
    __nv_bfloat16 h2 = __float2bfloat16(v.z), h3 = __float2bfloat16(v.w);
    uint2 hh, ll;
    hh.x = (uint32_t)__bfloat16_as_ushort(h0) | ((uint32_t)__bfloat16_as_ushort(h1) << 16);
    hh.y = (uint32_t)__bfloat16_as_ushort(h2) | ((uint32_t)__bfloat16_as_ushort(h3) << 16);
    ll.x = packbf(v.x - __bfloat162float(h0), v.y - __bfloat162float(h1));
    ll.y = packbf(v.z - __bfloat162float(h2), v.w - __bfloat162float(h3));
    ((uint2*)g_x_hi)[idx] = hh;
    ((uint2*)g_x_lo)[idx] = ll;
}

// ---------------- weight concat (+ elmax init) ----------------
__global__ void k_prep_w(const float* __restrict__ W_gat, const float* __restrict__ attn_l,
                         const float* __restrict__ attn_r, const float* __restrict__ gate_m_W,
                         const float* __restrict__ merge_W, const float* __restrict__ gate_fn_W)
{
    int n = blockIdx.x, k = threadIdx.x;
    if (n == 0 && k < 4) g_elmax[k] = fenc(-1e30f);
    float v = 0.f;
    if (n < 256)      v = W_gat[k * 256 + n];
    else if (n < 320) v = gate_m_W[k * 64 + (n - 256)];
    else if (n < 384) v = merge_W[k * 64 + (n - 320)];
    else if (n < 388) v = gate_fn_W[k * 4 + (n - 384)];
    else if (n < 392) v = gate_fn_W[(320 + k) * 4 + (n - 388)];
    else if (n < 396) {
        int h = n - 392; float s = 0.f;
        for (int o = 0; o < 64; o++) s += W_gat[k * 256 + h * 64 + o] * attn_l[h * 64 + o];
        v = s;
    } else if (n < 400) {
        int h = n - 396; float s = 0.f;
        for (int o = 0; o < 64; o++) s += W_gat[k * 256 + h * 64 + o] * attn_r[h * 64 + o];
        v = s;
    }
    __nv_bfloat16 hi = __float2bfloat16(v);
    g_wcat_hi[n * 256 + k] = __bfloat16_as_ushort(hi);
    g_wcat_lo[n * 256 + k] = __bfloat16_as_ushort(__float2bfloat16(v - __bfloat162float(hi)));
}

// ---------------- pipelined HMMA GEMM: 4 buffers, loads issued before compute ----------------
#define STAGE 36864
#define GEMM_SMEM (4 * STAGE)

__global__ __launch_bounds__(256, 1) void k_gemm_mma(
    const float* __restrict__ gate_m_b, const float* __restrict__ merge_b,
    float* __restrict__ out)
{
    extern __shared__ __align__(16) char sm[];
    uint32_t sb = smem_u32(sm);
    int tid = threadIdx.x, w = tid >> 5, lane = tid & 31;
    int r0 = blockIdx.x * 128;
    int nb = blockIdx.y * 256;
    int wm = (w & 1) * 64, wn = (w >> 1) * 64;

    int arow = tid >> 1, akg = tid & 1;
    int agr = r0 + arow;
    uint32_t aok = (agr < N_NODES) ? 16u : 0u;
    if (agr >= N_NODES) agr = 0;
    const unsigned short* axh = g_x_hi + (size_t)agr * 256 + akg * 8;
    const unsigned short* axl = g_x_lo + (size_t)agr * 256 + akg * 8;
    uint32_t adst = arow * 48 + akg * 16;

    auto load_chunk = [&](int ch, uint32_t base) {
        int k0 = ch * 16;
        cpa16(base + adst, axh + k0, aok);
        cpa16(base + 6144 + adst, axl + k0, aok);
        #pragma unroll
        for (int i = 0; i < 2; i++) {
            int q = tid + i * 256;
            int row = q >> 1, kg = q & 1;
            uint32_t d = base + 12288 + row * 48 + kg * 16;
            cpa16(d, g_wcat_hi + (size_t)(nb + row) * 256 + k0 + kg * 8, 16);
            cpa16(d + 12288, g_wcat_lo + (size_t)(nb + row) * 256 + k0 + kg * 8, 16);
        }
    };

    float acc[4][8][4];
    #pragma unroll
    for (int a = 0; a < 4; a++)
        #pragma unroll
        for (int b = 0; b < 8; b++)
            #pragma unroll
            for (int c = 0; c < 4; c++) acc[a][b][c] = 0.f;

    #pragma unroll
    for (int p = 0; p < 3; p++) { load_chunk(p, sb + p * STAGE); CPA_COMMIT(); }

    for (int ch = 0; ch < 16; ch++) {
        CPA_WAIT2();
        __syncthreads();
        // issue next loads FIRST (buffer of ch-1 is dead after the barrier)
        if (ch + 3 < 16) load_chunk(ch + 3, sb + ((ch + 3) & 3) * STAGE);
        CPA_COMMIT();

        uint32_t base = sb + (ch & 3) * STAGE;
        uint32_t aH[4][4], aL[4][4], bf[4][4];
        int ar = wm + (lane & 7) + ((lane & 8) ? 8 : 0);
        int ac = ((lane & 16) ? 16 : 0);
        #pragma unroll
        for (int mt = 0; mt < 4; mt++) {
            ldsm4(aH[mt], base + (ar + mt * 16) * 48 + ac);
            ldsm4(aL[mt], base + 6144 + (ar + mt * 16) * 48 + ac);
        }
        int br = wn + (lane & 7) + ((lane & 16) ? 8 : 0);
        int bc = ((lane & 8) ? 16 : 0);
        #pragma unroll
        for (int nt = 0; nt < 4; nt++)
            ldsm4(bf[nt], base + 12288 + (br + nt * 16) * 48 + bc);
        #pragma unroll
        for (int mt = 0; mt < 4; mt++)
            #pragma unroll
            for (int nt = 0; nt < 4; nt++) {
                mma16816(acc[mt][nt * 2],     aH[mt], &bf[nt][0]);
                mma16816(acc[mt][nt * 2 + 1], aH[mt], &bf[nt][2]);
                mma16816(acc[mt][nt * 2],     aL[mt], &bf[nt][0]);
                mma16816(acc[mt][nt * 2 + 1], aL[mt], &bf[nt][2]);
            }
        #pragma unroll
        for (int nt = 0; nt < 4; nt++)
            ldsm4(bf[nt], base + 24576 + (br + nt * 16) * 48 + bc);
        #pragma unroll
        for (int mt = 0; mt < 4; mt++)
            #pragma unroll
            for (int nt = 0; nt < 4; nt++) {
                mma16816(acc[mt][nt * 2],     aH[mt], &bf[nt][0]);
                mma16816(acc[mt][nt * 2 + 1], aH[mt], &bf[nt][2]);
            }
    }

    // epilogue
    int gcbase = nb + wn;
    #pragma unroll
    for (int nt = 0; nt < 8; nt++) {
        int gc = gcbase + nt * 8 + 2 * (lane & 3);
        if (gc >= 400) continue;
        float b0 = 0.f, b1 = 0.f;
        if (gc >= 256 && gc < 320) { b0 = gate_m_b[gc - 256]; b1 = gate_m_b[gc - 255]; }
        else if (gc >= 320 && gc < 384) { b0 = merge_b[gc - 320]; b1 = merge_b[gc - 319]; }
        #pragma unroll
        for (int mt = 0; mt < 4; mt++) {
            int row0 = r0 + wm + mt * 16 + (lane >> 2);
            #pragma unroll
            for (int h = 0; h < 2; h++) {
                int row = row0 + h * 8;
                if (row >= N_NODES) continue;
                float v0 = acc[mt][nt][h * 2] + b0;
                float v1 = acc[mt][nt][h * 2 + 1] + b1;
                if (gc < 256)
                    ((uint32_t*)g_featb)[(size_t)row * 128 + (gc >> 1)] = packbf(v0, v1);
                else if (gc < 320)
                    ((uint32_t*)g_zb)[row * 32 + ((gc - 256) >> 1)] = packbf(v0, v1);
                else if (gc < 384)
                    *(float2*)(out + (size_t)row * 64 + (gc - 320)) = make_float2(v0, v1);
                else {
                    int cc = gc - 384;
                    float* bp = cc < 4 ? (float*)g_xc : cc < 8 ? (float*)g_px
                              : cc < 12 ? (float*)g_el : (float*)g_er;
                    *(float2*)(bp + (size_t)row * 4 + (cc & 3)) = make_float2(v0, v1);
                }
            }
        }
    }
}

// ---------------- global per-head max of el ----------------
__global__ __launch_bounds__(256) void k_elmax() {
    __shared__ uint32_t red[256];
    int t = threadIdx.x;
    int h = t & 3;
    const float* elf = (const float*)g_el;
    uint32_t local = fenc(-1e30f);
    for (int i = blockIdx.x * 64 + (t >> 2); i < N_NODES; i += gridDim.x * 64)
        local = max(local, fenc(elf[4 * i + h]));
    red[t] = local;
    __syncthreads();
    #pragma unroll
    for (int off = 128; off >= 4; off >>= 1) {
        if (t < off) red[t] = max(red[t], red[t + off]);
        __syncthreads();
    }
    if (t < 4) atomicMax(&g_elmax[t], red[t]);
}

// ---------------- fused aggregation + gate + merge2 ----------------
__global__ __launch_bounds__(256) void k_agg(
    const float* __restrict__ gate_fn_W, const float* __restrict__ gate_fn_b,
    const float* __restrict__ W2, float* __restrict__ out)
{
    __shared__ float4 s_wm[64];
    __shared__ float  s_W2[64 * 64];
    __shared__ float  s_gat[8][64];
    __shared__ float4 s_gb;
    int tid = threadIdx.x;
    if (tid < 64) s_wm[tid] = ((const float4*)gate_fn_W)[256 + tid];
    if (tid == 64) s_gb = *(const float4*)gate_fn_b;
    #pragma unroll
    for (int i = 0; i < 16; i++) s_W2[tid + i * 256] = W2[tid + i * 256];
    __syncthreads();

    int lane = tid & 31, w = tid >> 5;
    int n = blockIdx.x * 8 + w;
    if (n >= N_NODES) return;

    int beg = g_off[n], end = g_off[n + 1];
    int deg = end - beg;
    if (deg == 0) return;

    const int h = lane >> 3;
    const float* elf = (const float*)g_el;
    const float* pxf = (const float*)g_px;
    const uint32_t* zb = (const uint32_t*)g_zb;
    const uint4* fb = (const uint4*)g_featb;

    float er_h = ((const float*)(g_er + n))[h];
    float m_h = lrelu(fdec(g_elmax[h]) + er_h);

    float facc[8];
    #pragma unroll
    for (int k = 0; k < 8; k++) facc[k] = 0.f;
    float sH = 0.f, pxs = 0.f;
    float mzx = -1e30f, mzy = -1e30f;

    int j = beg;
    for (; j + 4 <= end; j += 4) {
        int s0 = g_srcs[j], s1 = g_srcs[j + 1], s2 = g_srcs[j + 2], s3 = g_srcs[j + 3];
        float el0 = elf[4 * s0 + h], el1 = elf[4 * s1 + h];
        float el2 = elf[4 * s2 + h], el3 = elf[4 * s3 + h];
        float p0 = pxf[4 * s0 + h], p1 = pxf[4 * s1 + h];
        float p2 = pxf[4 * s2 + h], p3 = pxf[4 * s3 + h];
        uint32_t z0 = zb[s0 * 32 + lane], z1 = zb[s1 * 32 + lane];
        uint32_t z2 = zb[s2 * 32 + lane], z3 = zb[s3 * 32 + lane];
        uint4 f0 = fb[(size_t)s0 * 32 + lane], f1 = fb[(size_t)s1 * 32 + lane];
        uint4 f2 = fb[(size_t)s2 * 32 + lane], f3 = fb[(size_t)s3 * 32 + lane];

        float ex0 = __expf(lrelu(el0 + er_h) - m_h);
        float ex1 = __expf(lrelu(el1 + er_h) - m_h);
        float ex2 = __expf(lrelu(el2 + er_h) - m_h);
        float ex3 = __expf(lrelu(el3 + er_h) - m_h);
        sH += (ex0 + ex1) + (ex2 + ex3);
        pxs += (p0 + p1) + (p2 + p3);
        mzx = fmaxf(fmaxf(mzx, bflo(z0)), fmaxf(bflo(z1), fmaxf(bflo(z2), bflo(z3))));
        mzy = fmaxf(fmaxf(mzy, bfhi(z0)), fmaxf(bfhi(z1), fmaxf(bfhi(z2), bfhi(z3))));

        facc[0] = fmaf(bflo(f0.x), ex0, fmaf(bflo(f1.x), ex1, fmaf(bflo(f2.x), ex2, fmaf(bflo(f3.x), ex3, facc[0]))));
        facc[1] = fmaf(bfhi(f0.x), ex0, fmaf(bfhi(f1.x), ex1, fmaf(bfhi(f2.x), ex2, fmaf(bfhi(f3.x), ex3, facc[1]))));
        facc[2] = fmaf(bflo(f0.y), ex0, fmaf(bflo(f1.y), ex1, fmaf(bflo(f2.y), ex2, fmaf(bflo(f3.y), ex3, facc[2]))));
        facc[3] = fmaf(bfhi(f0.y), ex0, fmaf(bfhi(f1.y), ex1, fmaf(bfhi(f2.y), ex2, fmaf(bfhi(f3.y), ex3, facc[3]))));
        facc[4] = fmaf(bflo(f0.z), ex0, fmaf(bflo(f1.z), ex1, fmaf(bflo(f2.z), ex2, fmaf(bflo(f3.z), ex3, facc[4]))));
        facc[5] = fmaf(bfhi(f0.z), ex0, fmaf(bfhi(f1.z), ex1, fmaf(bfhi(f2.z), ex2, fmaf(bfhi(f3.z), ex3, facc[5]))));
        facc[6] = fmaf(bflo(f0.w), ex0, fmaf(bflo(f1.w), ex1, fmaf(bflo(f2.w), ex2, fmaf(bflo(f3.w), ex3, facc[6]))));
        facc[7] = fmaf(bfhi(f0.w), ex0, fmaf(bfhi(f1.w), ex1, fmaf(bfhi(f2.w), ex2, fmaf(bfhi(f3.w), ex3, facc[7]))));
    }
    for (; j < end; j++) {
        int s = g_srcs[j];
        float ex = __expf(lrelu(elf[4 * s + h] + er_h) - m_h);
        sH += ex;
        pxs += pxf[4 * s + h];
        uint32_t zr = zb[s * 32 + lane];
        mzx = fmaxf(mzx, bflo(zr)); mzy = fmaxf(mzy, bfhi(zr));
        uint4 fv = fb[(size_t)s * 32 + lane];
        facc[0] = fmaf(bflo(fv.x), ex, facc[0]);
        facc[1] = fmaf(bfhi(fv.x), ex, facc[1]);
        facc[2] = fmaf(bflo(fv.y), ex, facc[2]);
        facc[3] = fmaf(bfhi(fv.y), ex, facc[3]);
        facc[4] = fmaf(bflo(fv.z), ex, facc[4]);
        facc[5] = fmaf(bfhi(fv.z), ex, facc[5]);
        facc[6] = fmaf(bflo(fv.w), ex, facc[6]);
        facc[7] = fmaf(bfhi(fv.w), ex, facc[7]);
    }

    float4 wA = s_wm[2 * lane], wB = s_wm[2 * lane + 1];
    float4 gl;
    gl.x = mzx * wA.x + mzy * wB.x;
    gl.y = mzx * wA.y + mzy * wB.y;
    gl.z = mzx * wA.z + mzy * wB.z;
    gl.w = mzx * wA.w + mzy * wB.w;
    #pragma unroll
    for (int d = 16; d; d >>= 1) {
        gl.x += __shfl_xor_sync(0xffffffffu, gl.x, d);
        gl.y += __shfl_xor_sync(0xffffffffu, gl.y, d);
        gl.z += __shfl_xor_sync(0xffffffffu, gl.z, d);
        gl.w += __shfl_xor_sync(0xffffffffu, gl.w, d);
    }
    float invdeg = 1.f / (float)deg;
    float t = sel4(g_xc[n], h) + pxs * invdeg + sel4(gl, h) + sel4(s_gb, h);
    float gate = 1.f / (1.f + __expf(-t));
    float c = gate / fmaxf(sH, 1e-16f);

    float r[8];
    #pragma unroll
    for (int k = 0; k < 8; k++) {
        float v = facc[k] * c;
        v += __shfl_xor_sync(0xffffffffu, v, 8);
        v += __shfl_xor_sync(0xffffffffu, v, 16);
        r[k] = v * 0.25f;
    }
    if (lane < 8) {
        #pragma unroll
        for (int k = 0; k < 8; k++) s_gat[w][8 * lane + k] = r[k];
    }
    __syncwarp();

    float o0 = 0.f, o1 = 0.f;
    #pragma unroll 4
    for (int k = 0; k < 64; k++) {
        float g = s_gat[w][k];
        float2 w2 = ((const float2*)s_W2)[k * 32 + lane];
        o0 = fmaf(g, w2.x, o0);
        o1 = fmaf(g, w2.y, o1);
    }
    float2* op = (float2*)(out + (size_t)n * 64) + lane;
    float2 o = *op;
    o.x += o0; o.y += o1;
    *op = o;
}

// ---------------- launch: fork-join overlap of CSR and GEMM chains ----------------
extern "C" void kernel_launch(void* const* d_in, const int* in_sizes, int n_in,
                              void* d_out, int out_size)
{
    const float* x         = (const float*)d_in[0];
    const int*   src       = (const int*)d_in[1];
    const int*   dst       = (const int*)d_in[2];
    const float* W_gat     = (const float*)d_in[3];
    const float* attn_l    = (const float*)d_in[4];
    const float* attn_r    = (const float*)d_in[5];
    const float* gate_m_W  = (const float*)d_in[6];
    const float* gate_m_b  = (const float*)d_in[7];
    const float* gate_fn_W = (const float*)d_in[8];
    const float* gate_fn_b = (const float*)d_in[9];
    const float* merge_W   = (const float*)d_in[10];
    const float* merge_b   = (const float*)d_in[11];
    float* out = (float*)d_out;

    static cudaStream_t s_csr = nullptr;
    static cudaEvent_t  ev_fork = nullptr, ev_join = nullptr;
    static bool init_done = false;
    if (!init_done) {
        cudaStreamCreateWithFlags(&s_csr, cudaStreamNonBlocking);
        cudaEventCreateWithFlags(&ev_fork, cudaEventDisableTiming);
        cudaEventCreateWithFlags(&ev_join, cudaEventDisableTiming);
        cudaFuncSetAttribute(k_gemm_mma, cudaFuncAttributeMaxDynamicSharedMemorySize, GEMM_SMEM);
        init_done = true;
    }

    // fork: CSR chain on side stream
    cudaEventRecord(ev_fork, 0);
    cudaStreamWaitEvent(s_csr, ev_fork, 0);
    k_zero_deg<<<(N_NODES + 255) / 256, 256, 0, s_csr>>>();
    k_hist<<<(N_EDGES + 255) / 256, 256, 0, s_csr>>>(dst);
    k_scan<<<1, 1024, 0, s_csr>>>();
    k_scatter<<<(N_EDGES + 255) / 256, 256, 0, s_csr>>>(src, dst);
    cudaEventRecord(ev_join, s_csr);

    // main stream: GEMM chain
    k_split_x<<<(N_NODES * 64 + 255) / 256, 256>>>(x);
    k_prep_w<<<NCOLS, 256>>>(W_gat, attn_l, attn_r, gate_m_W, merge_W, gate_fn_W);
    k_gemm_mma<<<dim3((N_NODES + 127) / 128, 2), 256, GEMM_SMEM>>>(gate_m_b, merge_b, out);
    k_elmax<<<128, 256>>>();

    // join, then aggregate
    cudaStreamWaitEvent(0, ev_join, 0);
    k_agg<<<(N_NODES + 7) / 8, 256>>>(gate_fn_W, gate_fn_b, merge_W + 256 * 64, out);
}